// round 8
// baseline (speedup 1.0000x reference)
#include <cuda_runtime.h>
#include <cuda_bf16.h>
#include <math.h>

#define NN   100000
#define EE   600000
#define FINN 256
#define HH   128
#define CC   47
#define NOUTT 10000

// ---------------- scratch (device globals; no allocations allowed) ----------
__device__ float g_bufA[(size_t)NN * HH];
__device__ float g_bufB[(size_t)NN * HH];
__device__ float g_bufC[(size_t)NN * HH];
__device__ float g_acc [(size_t)NN * HH * 2];   // interleaved {sum(w), sum(m*w)}

// ======================= TF32 mma helpers ===================================
__device__ __forceinline__ unsigned f2tf32(float x) {
    unsigned r;
    asm("cvt.rna.tf32.f32 %0, %1;" : "=r"(r) : "f"(x));
    return r;
}

__device__ __forceinline__ void mma_tf32(float* d, const unsigned* a, const unsigned* b) {
    asm volatile(
        "mma.sync.aligned.m16n8k8.row.col.f32.tf32.tf32.f32 "
        "{%0,%1,%2,%3}, {%4,%5,%6,%7}, {%8,%9}, {%0,%1,%2,%3};"
        : "+f"(d[0]), "+f"(d[1]), "+f"(d[2]), "+f"(d[3])
        : "r"(a[0]), "r"(a[1]), "r"(a[2]), "r"(a[3]), "r"(b[0]), "r"(b[1]));
}

// ---------------- TF32 split GEMM: C[M,128] = A'[M,K] @ W[K,128] + bias -----
// AMODE 0: A' = A (lda = K).  AMODE 1: A' = acc.mw/(acc.w+eps) + A (lda = 128),
//          and acc is re-zeroed in place after being read (fused zeroing).
// resid row index via rmap (identity if null). CTA: 256 thr, tile 128x128.
#define APITCH 36
#define BPITCH 136
#define GSMEM_U (2 * 128 * APITCH + 2 * 32 * BPITCH)   // uints
#define GSMEM_B (GSMEM_U * 4)

template<int AMODE>
__global__ __launch_bounds__(256, 2) void gemm_mma_kernel(
    const float* __restrict__ A, int K,
    float*       __restrict__ accb,
    const float* __restrict__ W,
    const float* __restrict__ bias,
    const float* __restrict__ resid,
    const int*   __restrict__ rmap,
    float* __restrict__ C, int M)
{
    extern __shared__ unsigned smem_u[];
    unsigned* Ah = smem_u;                       // [128][APITCH]
    unsigned* Al = Ah + 128 * APITCH;
    unsigned* Bh = Al + 128 * APITCH;            // [32][BPITCH]
    unsigned* Bl = Bh + 32 * BPITCH;

    const int tid  = threadIdx.x;
    const int wid  = tid >> 5, lane = tid & 31;
    const int wr   = wid >> 2, wc = wid & 3;      // warp 2x4 grid
    const int qid  = lane >> 2, qtr = lane & 3;   // quad row / thread-in-quad
    const int bm   = blockIdx.x * 128;

    const int arow  = tid >> 1;
    const int apart = (tid & 1) * 16;
    const int agrow = bm + arow;
    const bool ain  = agrow < M;
    const int brow = tid >> 3;
    const int bcol = (tid & 7) * 16;

    float acc[4][4][4];
#pragma unroll
    for (int i = 0; i < 4; i++)
#pragma unroll
        for (int j = 0; j < 4; j++)
#pragma unroll
            for (int q = 0; q < 4; q++) acc[i][j][q] = 0.f;

    const int nchunks = K >> 5;
    for (int ch = 0; ch < nchunks; ch++) {
        const int k0 = ch * 32;
        // ---- load + split A tile ----
        {
            float v[16];
            if (ain) {
                if (AMODE == 0) {
                    const float4* ap = (const float4*)(A + (size_t)agrow * K + k0 + apart);
#pragma unroll
                    for (int j = 0; j < 4; j++) {
                        float4 t = ap[j];
                        v[j * 4 + 0] = t.x; v[j * 4 + 1] = t.y;
                        v[j * 4 + 2] = t.z; v[j * 4 + 3] = t.w;
                    }
                } else {
                    float4* cp = (float4*)(accb + (size_t)agrow * 256 + 2 * (k0 + apart));
                    const float4* ap = (const float4*)(A + (size_t)agrow * 128 + k0 + apart);
#pragma unroll
                    for (int j = 0; j < 8; j++) {
                        float4 t = cp[j];
                        v[j * 2 + 0] = t.y / (t.x + 1e-16f);
                        v[j * 2 + 1] = t.w / (t.z + 1e-16f);
                        cp[j] = make_float4(0.f, 0.f, 0.f, 0.f);  // fused re-zero
                    }
#pragma unroll
                    for (int j = 0; j < 4; j++) {
                        float4 t = ap[j];
                        v[j * 4 + 0] += t.x; v[j * 4 + 1] += t.y;
                        v[j * 4 + 2] += t.z; v[j * 4 + 3] += t.w;
                    }
                }
            } else {
#pragma unroll
                for (int j = 0; j < 16; j++) v[j] = 0.f;
            }
            unsigned* dh = Ah + arow * APITCH + apart;
            unsigned* dl = Al + arow * APITCH + apart;
#pragma unroll
            for (int j = 0; j < 4; j++) {
                uint4 h4, l4;
                h4.x = f2tf32(v[j*4+0]); l4.x = f2tf32(v[j*4+0] - __uint_as_float(h4.x));
                h4.y = f2tf32(v[j*4+1]); l4.y = f2tf32(v[j*4+1] - __uint_as_float(h4.y));
                h4.z = f2tf32(v[j*4+2]); l4.z = f2tf32(v[j*4+2] - __uint_as_float(h4.z));
                h4.w = f2tf32(v[j*4+3]); l4.w = f2tf32(v[j*4+3] - __uint_as_float(h4.w));
                *(uint4*)(dh + j * 4) = h4;
                *(uint4*)(dl + j * 4) = l4;
            }
        }
        // ---- load + split B tile ----
        {
            const float4* wp = (const float4*)(W + (size_t)(k0 + brow) * 128 + bcol);
            unsigned* dh = Bh + brow * BPITCH + bcol;
            unsigned* dl = Bl + brow * BPITCH + bcol;
#pragma unroll
            for (int j = 0; j < 4; j++) {
                float4 t = wp[j];
                uint4 h4, l4;
                h4.x = f2tf32(t.x); l4.x = f2tf32(t.x - __uint_as_float(h4.x));
                h4.y = f2tf32(t.y); l4.y = f2tf32(t.y - __uint_as_float(h4.y));
                h4.z = f2tf32(t.z); l4.z = f2tf32(t.z - __uint_as_float(h4.z));
                h4.w = f2tf32(t.w); l4.w = f2tf32(t.w - __uint_as_float(h4.w));
                *(uint4*)(dh + j * 4) = h4;
                *(uint4*)(dl + j * 4) = l4;
            }
        }
        __syncthreads();

        // ---- 4 k-steps of 8: term-major MMA schedule (16-deep reuse dist) ----
#pragma unroll
        for (int ks = 0; ks < 4; ks++) {
            const int kb = ks * 8;
            unsigned ahi[4][4], alo[4][4];
#pragma unroll
            for (int mf = 0; mf < 4; mf++) {
                int base = (wr * 64 + mf * 16 + qid) * APITCH + kb + qtr;
                ahi[mf][0] = Ah[base];
                ahi[mf][1] = Ah[base + 8 * APITCH];
                ahi[mf][2] = Ah[base + 4];
                ahi[mf][3] = Ah[base + 8 * APITCH + 4];
                alo[mf][0] = Al[base];
                alo[mf][1] = Al[base + 8 * APITCH];
                alo[mf][2] = Al[base + 4];
                alo[mf][3] = Al[base + 8 * APITCH + 4];
            }
            unsigned bhi[4][2], blo[4][2];
#pragma unroll
            for (int nf = 0; nf < 4; nf++) {
                int base = (kb + qtr) * BPITCH + wc * 32 + nf * 8 + qid;
                bhi[nf][0] = Bh[base];
                bhi[nf][1] = Bh[base + 4 * BPITCH];
                blo[nf][0] = Bl[base];
                blo[nf][1] = Bl[base + 4 * BPITCH];
            }
#pragma unroll
            for (int mf = 0; mf < 4; mf++)
#pragma unroll
                for (int nf = 0; nf < 4; nf++)
                    mma_tf32(acc[mf][nf], ahi[mf], bhi[nf]);
#pragma unroll
            for (int mf = 0; mf < 4; mf++)
#pragma unroll
                for (int nf = 0; nf < 4; nf++)
                    mma_tf32(acc[mf][nf], ahi[mf], blo[nf]);
#pragma unroll
            for (int mf = 0; mf < 4; mf++)
#pragma unroll
                for (int nf = 0; nf < 4; nf++)
                    mma_tf32(acc[mf][nf], alo[mf], bhi[nf]);
        }
        __syncthreads();
    }

    // ---- epilogue: bias (+resid via rmap), write C ----
#pragma unroll
    for (int mf = 0; mf < 4; mf++) {
        int r0 = bm + wr * 64 + mf * 16 + qid;
        int rr0 = 0, rr1 = 0;
        if (resid) {
            if (r0 < M)     rr0 = rmap ? __ldg(rmap + r0)     : r0;
            if (r0 + 8 < M) rr1 = rmap ? __ldg(rmap + r0 + 8) : r0 + 8;
        }
#pragma unroll
        for (int nf = 0; nf < 4; nf++) {
            int c0 = wc * 32 + nf * 8 + qtr * 2;
            float2 bv = *(const float2*)&bias[c0];
            if (r0 < M) {
                float2 o;
                o.x = acc[mf][nf][0] + bv.x;
                o.y = acc[mf][nf][1] + bv.y;
                if (resid) {
                    float2 rv = *(const float2*)&resid[(size_t)rr0 * 128 + c0];
                    o.x += rv.x; o.y += rv.y;
                }
                *(float2*)&C[(size_t)r0 * 128 + c0] = o;
            }
            if (r0 + 8 < M) {
                float2 o;
                o.x = acc[mf][nf][2] + bv.x;
                o.y = acc[mf][nf][3] + bv.y;
                if (resid) {
                    float2 rv = *(const float2*)&resid[(size_t)rr1 * 128 + c0];
                    o.x += rv.x; o.y += rv.y;
                }
                *(float2*)&C[(size_t)(r0 + 8) * 128 + c0] = o;
            }
        }
    }
}

// ---------------- zero kernel ------------------------------------------------
__global__ void zero_kernel(float4* __restrict__ p, int n4) {
    int i = blockIdx.x * blockDim.x + threadIdx.x;
    if (i < n4) p[i] = make_float4(0.f, 0.f, 0.f, 0.f);
}

// ---------------- edge pass: fused softmax num/denom via vector RED ---------
__global__ void edge_kernel(const float* __restrict__ h,
                            const int*   __restrict__ src,
                            const int*   __restrict__ dst,
                            float*       __restrict__ acc, int E) {
    int gw   = (blockIdx.x * blockDim.x + threadIdx.x) >> 5;
    int lane = threadIdx.x & 31;
    if (gw >= E) return;
    int s = __ldg(src + gw);
    int d = __ldg(dst + gw);
    float4 v = *(const float4*)&h[s * HH + lane * 4];
    float m0 = fmaxf(v.x, 0.f) + 1e-7f;
    float m1 = fmaxf(v.y, 0.f) + 1e-7f;
    float m2 = fmaxf(v.z, 0.f) + 1e-7f;
    float m3 = fmaxf(v.w, 0.f) + 1e-7f;
    float w0 = __expf(m0), w1 = __expf(m1), w2 = __expf(m2), w3 = __expf(m3);
    float* base = acc + d * (2 * HH) + lane * 8;
    asm volatile("red.global.add.v4.f32 [%0], {%1,%2,%3,%4};"
                 :: "l"(base), "f"(w0), "f"(m0 * w0), "f"(w1), "f"(m1 * w1) : "memory");
    asm volatile("red.global.add.v4.f32 [%0], {%1,%2,%3,%4};"
                 :: "l"(base + 4), "f"(w2), "f"(m2 * w2), "f"(w3), "f"(m3 * w3) : "memory");
}

// ---------------- LayerNorm + ReLU (warp per row, optional input gather) ----
__global__ void ln_relu_kernel(const float* __restrict__ in,
                               const int*   __restrict__ map,
                               const float* __restrict__ g,
                               const float* __restrict__ b,
                               float* __restrict__ out, int M) {
    int gw   = (blockIdx.x * blockDim.x + threadIdx.x) >> 5;
    int lane = threadIdx.x & 31;
    if (gw >= M) return;
    int srow = map ? __ldg(map + gw) : gw;
    float4 v = *(const float4*)&in[(size_t)srow * HH + lane * 4];
    float s = v.x + v.y + v.z + v.w;
#pragma unroll
    for (int o = 16; o; o >>= 1) s += __shfl_xor_sync(0xffffffffu, s, o);
    float mu = s * (1.f / 128.f);
    float dx = v.x - mu, dy = v.y - mu, dz = v.z - mu, dw = v.w - mu;
    float q = dx * dx + dy * dy + dz * dz + dw * dw;
#pragma unroll
    for (int o = 16; o; o >>= 1) q += __shfl_xor_sync(0xffffffffu, q, o);
    float rs = rsqrtf(q * (1.f / 128.f) + 1e-5f);
    float4 gv = *(const float4*)&g[lane * 4];
    float4 bv = *(const float4*)&b[lane * 4];
    float4 o4;
    o4.x = fmaxf(dx * rs * gv.x + bv.x, 0.f);
    o4.y = fmaxf(dy * rs * gv.y + bv.y, 0.f);
    o4.z = fmaxf(dz * rs * gv.z + bv.z, 0.f);
    o4.w = fmaxf(dw * rs * gv.w + bv.w, 0.f);
    *(float4*)&out[gw * HH + lane * 4] = o4;
}

// ---------------- final: composed gather + LN + ReLU + pred + log_softmax --
__global__ void final_kernel(const float* __restrict__ h,
                             const int*   __restrict__ nmap,
                             const int*   __restrict__ fmap,
                             const float* __restrict__ g,
                             const float* __restrict__ b,
                             const float* __restrict__ pw,
                             const float* __restrict__ pb,
                             float* __restrict__ out) {
    __shared__ float sv[128];
    __shared__ float sl[CC];
    __shared__ float red[4];
    __shared__ float stats[2];
    int t = threadIdx.x;
    int lane = t & 31, warp = t >> 5;
    int row = __ldg(nmap + __ldg(fmap + blockIdx.x));
    float x = h[(size_t)row * HH + t];
    float s = x;
#pragma unroll
    for (int o = 16; o; o >>= 1) s += __shfl_xor_sync(0xffffffffu, s, o);
    if (lane == 0) red[warp] = s;
    __syncthreads();
    float mu = (red[0] + red[1] + red[2] + red[3]) * (1.f / 128.f);
    float d = x - mu;
    float q = d * d;
#pragma unroll
    for (int o = 16; o; o >>= 1) q += __shfl_xor_sync(0xffffffffu, q, o);
    __syncthreads();
    if (lane == 0) red[warp] = q;
    __syncthreads();
    float var = (red[0] + red[1] + red[2] + red[3]) * (1.f / 128.f);
    float rs = rsqrtf(var + 1e-5f);
    sv[t] = fmaxf(d * rs * g[t] + b[t], 0.f);
    __syncthreads();
    if (t < CC) {
        float a = pb[t];
#pragma unroll 8
        for (int k = 0; k < 128; k++) a += sv[k] * pw[k * CC + t];
        sl[t] = a;
    }
    __syncthreads();
    if (t == 0) {
        float mx = -1e30f;
        for (int c = 0; c < CC; c++) mx = fmaxf(mx, sl[c]);
        float se = 0.f;
        for (int c = 0; c < CC; c++) se += expf(sl[c] - mx);
        stats[0] = mx; stats[1] = logf(se);
    }
    __syncthreads();
    if (t < CC) out[blockIdx.x * CC + t] = sl[t] - stats[0] - stats[1];
}

// ---------------- host orchestration ----------------------------------------
extern "C" void kernel_launch(void* const* d_in, const int* in_sizes, int n_in,
                              void* d_out, int out_size) {
    const float* x        = (const float*)d_in[0];
    const int*   src      = (const int*)  d_in[1];
    const int*   dst      = (const int*)  d_in[2];
    const int*   node_map = (const int*)  d_in[3];
    const int*   fmap     = (const int*)  d_in[4];
    const float* enc_w    = (const float*)d_in[5];
    const float* enc_b    = (const float*)d_in[6];
    const float* gcn_w    = (const float*)d_in[7];
    const float* gcn_b    = (const float*)d_in[8];
    const float* ln_g     = (const float*)d_in[9];
    const float* ln_b     = (const float*)d_in[10];
    const float* pred_w   = (const float*)d_in[11];
    const float* pred_b   = (const float*)d_in[12];
    float* out = (float*)d_out;

    float *bA, *bB, *bC, *acc;
    cudaGetSymbolAddress((void**)&bA,  g_bufA);
    cudaGetSymbolAddress((void**)&bB,  g_bufB);
    cudaGetSymbolAddress((void**)&bC,  g_bufC);
    cudaGetSymbolAddress((void**)&acc, g_acc);

    cudaFuncSetAttribute(gemm_mma_kernel<0>, cudaFuncAttributeMaxDynamicSharedMemorySize, GSMEM_B);
    cudaFuncSetAttribute(gemm_mma_kernel<1>, cudaFuncAttributeMaxDynamicSharedMemorySize, GSMEM_B);

    const int gemmGrid = (NN + 127) / 128;
    const int accN4    = NN * HH * 2 / 4;
    const int zeroGrid = (accN4 + 255) / 256;
    const int edgeGrid = (EE * 32 + 255) / 256;
    const int rowGrid  = (NN * 32 + 255) / 256;

    // one up-front zero; gemm<1> re-zeros acc in place each layer
    zero_kernel<<<zeroGrid, 256>>>((float4*)acc, accN4);

    // encoder: h = x @ enc_w + enc_b                       -> bA
    gemm_mma_kernel<0><<<gemmGrid, 256, GSMEM_B>>>(x, FINN, nullptr, enc_w, enc_b,
                                                   nullptr, nullptr, bA, NN);

    // conv0: h = (agg(bA)+bA) @ W0 + b0                    -> bB
    edge_kernel<<<edgeGrid, 256>>>(bA, src, dst, acc, EE);
    gemm_mma_kernel<1><<<gemmGrid, 256, GSMEM_B>>>(bA, HH, acc, gcn_w, gcn_b,
                                                   nullptr, nullptr, bB, NN);

    // layer 1: h2 = relu(LN(bB)) -> bA; h = conv(h2,e0)+bB -> bC  (gather deferred)
    ln_relu_kernel<<<rowGrid, 256>>>(bB, nullptr, ln_g, ln_b, bA, NN);
    edge_kernel<<<edgeGrid, 256>>>(bA, src, dst, acc, EE);
    gemm_mma_kernel<1><<<gemmGrid, 256, GSMEM_B>>>(bA, HH, acc, gcn_w + HH * HH, gcn_b + HH,
                                                   bB, nullptr, bC, NN);

    // layer 2: h = bC[node_map0] (fused): h2 = relu(LN(h)) -> bB;
    //          h = conv(h2,e1) + bC[node_map0]             -> bA
    ln_relu_kernel<<<rowGrid, 256>>>(bC, node_map, ln_g + HH, ln_b + HH, bB, NN);
    edge_kernel<<<edgeGrid, 256>>>(bB, src + EE, dst + EE, acc, EE);
    gemm_mma_kernel<1><<<gemmGrid, 256, GSMEM_B>>>(bB, HH, acc, gcn_w + 2 * HH * HH,
                                                   gcn_b + 2 * HH, bC, node_map, bA, NN);

    // final: rows bA[node_map1[fmap[b]]]; LN+ReLU+pred+log_softmax
    final_kernel<<<NOUTT, 128>>>(bA, node_map + NN, fmap, ln_g + 2 * HH, ln_b + 2 * HH,
                                 pred_w, pred_b, out);
}

// round 10
// speedup vs baseline: 2.8320x; 2.8320x over previous
#include <cuda_runtime.h>
#include <cuda_bf16.h>
#include <math.h>

#define NN   100000
#define EE   600000
#define FINN 256
#define HH   128
#define CC   47
#define NOUTT 10000

// ---------------- scratch (device globals; no allocations allowed) ----------
__device__ float g_bufA[(size_t)NN * HH];
__device__ float g_bufB[(size_t)NN * HH];
__device__ float g_bufC[(size_t)NN * HH];
__device__ float g_acc [(size_t)NN * HH * 2];   // interleaved {sum(w), sum(m*w)}

// ======================= TF32 mma helpers ===================================
__device__ __forceinline__ unsigned f2tf32(float x) {
    unsigned r;
    asm("cvt.rna.tf32.f32 %0, %1;" : "=r"(r) : "f"(x));
    return r;
}

__device__ __forceinline__ void mma_tf32(float* d, const unsigned* a, const unsigned* b) {
    asm volatile(
        "mma.sync.aligned.m16n8k8.row.col.f32.tf32.tf32.f32 "
        "{%0,%1,%2,%3}, {%4,%5,%6,%7}, {%8,%9}, {%0,%1,%2,%3};"
        : "+f"(d[0]), "+f"(d[1]), "+f"(d[2]), "+f"(d[3])
        : "r"(a[0]), "r"(a[1]), "r"(a[2]), "r"(a[3]), "r"(b[0]), "r"(b[1]));
}

// ---------------- TF32 split GEMM: C[M,128] = A'[M,K] @ W[K,128] + bias -----
// AMODE 0: A' = A (lda = K).  AMODE 1: A' = acc.mw/(acc.w+eps) + A (lda = 128).
// resid row index via rmap (identity if null). CTA: 256 thr, tile 128x128.
// SMEM holds pre-split tf32 hi/lo; inner loop is pure LDS + MMA.
#define APITCH 36
#define BPITCH 136
#define GSMEM_U (2 * 128 * APITCH + 2 * 32 * BPITCH)   // uints
#define GSMEM_B (GSMEM_U * 4)

template<int AMODE>
__global__ __launch_bounds__(256, 2) void gemm_mma_kernel(
    const float* __restrict__ A, int K,
    const float* __restrict__ accb,
    const float* __restrict__ W,
    const float* __restrict__ bias,
    const float* __restrict__ resid,
    const int*   __restrict__ rmap,
    float* __restrict__ C, int M)
{
    extern __shared__ unsigned smem_u[];
    unsigned* Ah = smem_u;                       // [128][APITCH]
    unsigned* Al = Ah + 128 * APITCH;
    unsigned* Bh = Al + 128 * APITCH;            // [32][BPITCH]
    unsigned* Bl = Bh + 32 * BPITCH;

    const int tid  = threadIdx.x;
    const int wid  = tid >> 5, lane = tid & 31;
    const int wr   = wid >> 2, wc = wid & 3;      // warp 2x4 grid
    const int qid  = lane >> 2, qtr = lane & 3;   // quad row / thread-in-quad
    const int bm   = blockIdx.x * 128;

    const int arow  = tid >> 1;
    const int apart = (tid & 1) * 16;
    const int agrow = bm + arow;
    const bool ain  = agrow < M;
    const int brow = tid >> 3;
    const int bcol = (tid & 7) * 16;

    float acc[4][4][4];
#pragma unroll
    for (int i = 0; i < 4; i++)
#pragma unroll
        for (int j = 0; j < 4; j++)
#pragma unroll
            for (int q = 0; q < 4; q++) acc[i][j][q] = 0.f;

    const int nchunks = K >> 5;
    for (int ch = 0; ch < nchunks; ch++) {
        const int k0 = ch * 32;
        // ---- load + split A tile (loads batched; no interleaved stores) ----
        {
            float v[16];
            if (ain) {
                if (AMODE == 0) {
                    const float4* ap = (const float4*)(A + (size_t)agrow * K + k0 + apart);
#pragma unroll
                    for (int j = 0; j < 4; j++) {
                        float4 t = ap[j];
                        v[j * 4 + 0] = t.x; v[j * 4 + 1] = t.y;
                        v[j * 4 + 2] = t.z; v[j * 4 + 3] = t.w;
                    }
                } else {
                    const float4* cp = (const float4*)(accb + (size_t)agrow * 256 + 2 * (k0 + apart));
                    const float4* ap = (const float4*)(A + (size_t)agrow * 128 + k0 + apart);
#pragma unroll
                    for (int j = 0; j < 8; j++) {
                        float4 t = cp[j];
                        v[j * 2 + 0] = t.y / (t.x + 1e-16f);
                        v[j * 2 + 1] = t.w / (t.z + 1e-16f);
                    }
#pragma unroll
                    for (int j = 0; j < 4; j++) {
                        float4 t = ap[j];
                        v[j * 4 + 0] += t.x; v[j * 4 + 1] += t.y;
                        v[j * 4 + 2] += t.z; v[j * 4 + 3] += t.w;
                    }
                }
            } else {
#pragma unroll
                for (int j = 0; j < 16; j++) v[j] = 0.f;
            }
            unsigned* dh = Ah + arow * APITCH + apart;
            unsigned* dl = Al + arow * APITCH + apart;
#pragma unroll
            for (int j = 0; j < 4; j++) {
                uint4 h4, l4;
                h4.x = f2tf32(v[j*4+0]); l4.x = f2tf32(v[j*4+0] - __uint_as_float(h4.x));
                h4.y = f2tf32(v[j*4+1]); l4.y = f2tf32(v[j*4+1] - __uint_as_float(h4.y));
                h4.z = f2tf32(v[j*4+2]); l4.z = f2tf32(v[j*4+2] - __uint_as_float(h4.z));
                h4.w = f2tf32(v[j*4+3]); l4.w = f2tf32(v[j*4+3] - __uint_as_float(h4.w));
                *(uint4*)(dh + j * 4) = h4;
                *(uint4*)(dl + j * 4) = l4;
            }
        }
        // ---- load + split B tile ----
        {
            const float4* wp = (const float4*)(W + (size_t)(k0 + brow) * 128 + bcol);
            unsigned* dh = Bh + brow * BPITCH + bcol;
            unsigned* dl = Bl + brow * BPITCH + bcol;
#pragma unroll
            for (int j = 0; j < 4; j++) {
                float4 t = wp[j];
                uint4 h4, l4;
                h4.x = f2tf32(t.x); l4.x = f2tf32(t.x - __uint_as_float(h4.x));
                h4.y = f2tf32(t.y); l4.y = f2tf32(t.y - __uint_as_float(h4.y));
                h4.z = f2tf32(t.z); l4.z = f2tf32(t.z - __uint_as_float(h4.z));
                h4.w = f2tf32(t.w); l4.w = f2tf32(t.w - __uint_as_float(h4.w));
                *(uint4*)(dh + j * 4) = h4;
                *(uint4*)(dl + j * 4) = l4;
            }
        }
        __syncthreads();

        // ---- 4 k-steps of 8: term-major MMA schedule (16-deep reuse dist) ----
#pragma unroll
        for (int ks = 0; ks < 4; ks++) {
            const int kb = ks * 8;
            unsigned ahi[4][4], alo[4][4];
#pragma unroll
            for (int mf = 0; mf < 4; mf++) {
                int base = (wr * 64 + mf * 16 + qid) * APITCH + kb + qtr;
                ahi[mf][0] = Ah[base];
                ahi[mf][1] = Ah[base + 8 * APITCH];
                ahi[mf][2] = Ah[base + 4];
                ahi[mf][3] = Ah[base + 8 * APITCH + 4];
                alo[mf][0] = Al[base];
                alo[mf][1] = Al[base + 8 * APITCH];
                alo[mf][2] = Al[base + 4];
                alo[mf][3] = Al[base + 8 * APITCH + 4];
            }
            unsigned bhi[4][2], blo[4][2];
#pragma unroll
            for (int nf = 0; nf < 4; nf++) {
                int base = (kb + qtr) * BPITCH + wc * 32 + nf * 8 + qid;
                bhi[nf][0] = Bh[base];
                bhi[nf][1] = Bh[base + 4 * BPITCH];
                blo[nf][0] = Bl[base];
                blo[nf][1] = Bl[base + 4 * BPITCH];
            }
#pragma unroll
            for (int mf = 0; mf < 4; mf++)
#pragma unroll
                for (int nf = 0; nf < 4; nf++)
                    mma_tf32(acc[mf][nf], ahi[mf], bhi[nf]);
#pragma unroll
            for (int mf = 0; mf < 4; mf++)
#pragma unroll
                for (int nf = 0; nf < 4; nf++)
                    mma_tf32(acc[mf][nf], ahi[mf], blo[nf]);
#pragma unroll
            for (int mf = 0; mf < 4; mf++)
#pragma unroll
                for (int nf = 0; nf < 4; nf++)
                    mma_tf32(acc[mf][nf], alo[mf], bhi[nf]);
        }
        __syncthreads();
    }

    // ---- epilogue: bias (+resid via rmap), write C ----
#pragma unroll
    for (int mf = 0; mf < 4; mf++) {
        int r0 = bm + wr * 64 + mf * 16 + qid;
        int rr0 = 0, rr1 = 0;
        if (resid) {
            if (r0 < M)     rr0 = rmap ? __ldg(rmap + r0)     : r0;
            if (r0 + 8 < M) rr1 = rmap ? __ldg(rmap + r0 + 8) : r0 + 8;
        }
#pragma unroll
        for (int nf = 0; nf < 4; nf++) {
            int c0 = wc * 32 + nf * 8 + qtr * 2;
            float2 bv = *(const float2*)&bias[c0];
            if (r0 < M) {
                float2 o;
                o.x = acc[mf][nf][0] + bv.x;
                o.y = acc[mf][nf][1] + bv.y;
                if (resid) {
                    float2 rv = *(const float2*)&resid[(size_t)rr0 * 128 + c0];
                    o.x += rv.x; o.y += rv.y;
                }
                *(float2*)&C[(size_t)r0 * 128 + c0] = o;
            }
            if (r0 + 8 < M) {
                float2 o;
                o.x = acc[mf][nf][2] + bv.x;
                o.y = acc[mf][nf][3] + bv.y;
                if (resid) {
                    float2 rv = *(const float2*)&resid[(size_t)rr1 * 128 + c0];
                    o.x += rv.x; o.y += rv.y;
                }
                *(float2*)&C[(size_t)(r0 + 8) * 128 + c0] = o;
            }
        }
    }
}

// ---------------- zero kernel ------------------------------------------------
__global__ void zero_kernel(float4* __restrict__ p, int n4) {
    int i = blockIdx.x * blockDim.x + threadIdx.x;
    if (i < n4) p[i] = make_float4(0.f, 0.f, 0.f, 0.f);
}

// ---------------- edge pass: fused softmax num/denom via vector RED ---------
__global__ void edge_kernel(const float* __restrict__ h,
                            const int*   __restrict__ src,
                            const int*   __restrict__ dst,
                            float*       __restrict__ acc, int E) {
    int gw   = (blockIdx.x * blockDim.x + threadIdx.x) >> 5;
    int lane = threadIdx.x & 31;
    if (gw >= E) return;
    int s = __ldg(src + gw);
    int d = __ldg(dst + gw);
    float4 v = *(const float4*)&h[s * HH + lane * 4];
    float m0 = fmaxf(v.x, 0.f) + 1e-7f;
    float m1 = fmaxf(v.y, 0.f) + 1e-7f;
    float m2 = fmaxf(v.z, 0.f) + 1e-7f;
    float m3 = fmaxf(v.w, 0.f) + 1e-7f;
    float w0 = __expf(m0), w1 = __expf(m1), w2 = __expf(m2), w3 = __expf(m3);
    float* base = acc + d * (2 * HH) + lane * 8;
    asm volatile("red.global.add.v4.f32 [%0], {%1,%2,%3,%4};"
                 :: "l"(base), "f"(w0), "f"(m0 * w0), "f"(w1), "f"(m1 * w1) : "memory");
    asm volatile("red.global.add.v4.f32 [%0], {%1,%2,%3,%4};"
                 :: "l"(base + 4), "f"(w2), "f"(m2 * w2), "f"(w3), "f"(m3 * w3) : "memory");
}

// ---------------- LayerNorm + ReLU (warp per row, optional input gather) ----
__global__ void ln_relu_kernel(const float* __restrict__ in,
                               const int*   __restrict__ map,
                               const float* __restrict__ g,
                               const float* __restrict__ b,
                               float* __restrict__ out, int M) {
    int gw   = (blockIdx.x * blockDim.x + threadIdx.x) >> 5;
    int lane = threadIdx.x & 31;
    if (gw >= M) return;
    int srow = map ? __ldg(map + gw) : gw;
    float4 v = *(const float4*)&in[(size_t)srow * HH + lane * 4];
    float s = v.x + v.y + v.z + v.w;
#pragma unroll
    for (int o = 16; o; o >>= 1) s += __shfl_xor_sync(0xffffffffu, s, o);
    float mu = s * (1.f / 128.f);
    float dx = v.x - mu, dy = v.y - mu, dz = v.z - mu, dw = v.w - mu;
    float q = dx * dx + dy * dy + dz * dz + dw * dw;
#pragma unroll
    for (int o = 16; o; o >>= 1) q += __shfl_xor_sync(0xffffffffu, q, o);
    float rs = rsqrtf(q * (1.f / 128.f) + 1e-5f);
    float4 gv = *(const float4*)&g[lane * 4];
    float4 bv = *(const float4*)&b[lane * 4];
    float4 o4;
    o4.x = fmaxf(dx * rs * gv.x + bv.x, 0.f);
    o4.y = fmaxf(dy * rs * gv.y + bv.y, 0.f);
    o4.z = fmaxf(dz * rs * gv.z + bv.z, 0.f);
    o4.w = fmaxf(dw * rs * gv.w + bv.w, 0.f);
    *(float4*)&out[gw * HH + lane * 4] = o4;
}

// ---------------- final: composed gather + LN + ReLU + pred + log_softmax --
__global__ void final_kernel(const float* __restrict__ h,
                             const int*   __restrict__ nmap,
                             const int*   __restrict__ fmap,
                             const float* __restrict__ g,
                             const float* __restrict__ b,
                             const float* __restrict__ pw,
                             const float* __restrict__ pb,
                             float* __restrict__ out) {
    __shared__ float sv[128];
    __shared__ float sl[CC];
    __shared__ float red[4];
    __shared__ float stats[2];
    int t = threadIdx.x;
    int lane = t & 31, warp = t >> 5;
    int row = __ldg(nmap + __ldg(fmap + blockIdx.x));
    float x = h[(size_t)row * HH + t];
    float s = x;
#pragma unroll
    for (int o = 16; o; o >>= 1) s += __shfl_xor_sync(0xffffffffu, s, o);
    if (lane == 0) red[warp] = s;
    __syncthreads();
    float mu = (red[0] + red[1] + red[2] + red[3]) * (1.f / 128.f);
    float d = x - mu;
    float q = d * d;
#pragma unroll
    for (int o = 16; o; o >>= 1) q += __shfl_xor_sync(0xffffffffu, q, o);
    __syncthreads();
    if (lane == 0) red[warp] = q;
    __syncthreads();
    float var = (red[0] + red[1] + red[2] + red[3]) * (1.f / 128.f);
    float rs = rsqrtf(var + 1e-5f);
    sv[t] = fmaxf(d * rs * g[t] + b[t], 0.f);
    __syncthreads();
    if (t < CC) {
        float a = pb[t];
#pragma unroll 8
        for (int k = 0; k < 128; k++) a += sv[k] * pw[k * CC + t];
        sl[t] = a;
    }
    __syncthreads();
    if (t == 0) {
        float mx = -1e30f;
        for (int c = 0; c < CC; c++) mx = fmaxf(mx, sl[c]);
        float se = 0.f;
        for (int c = 0; c < CC; c++) se += expf(sl[c] - mx);
        stats[0] = mx; stats[1] = logf(se);
    }
    __syncthreads();
    if (t < CC) out[blockIdx.x * CC + t] = sl[t] - stats[0] - stats[1];
}

// ---------------- host orchestration ----------------------------------------
extern "C" void kernel_launch(void* const* d_in, const int* in_sizes, int n_in,
                              void* d_out, int out_size) {
    const float* x        = (const float*)d_in[0];
    const int*   src      = (const int*)  d_in[1];
    const int*   dst      = (const int*)  d_in[2];
    const int*   node_map = (const int*)  d_in[3];
    const int*   fmap     = (const int*)  d_in[4];
    const float* enc_w    = (const float*)d_in[5];
    const float* enc_b    = (const float*)d_in[6];
    const float* gcn_w    = (const float*)d_in[7];
    const float* gcn_b    = (const float*)d_in[8];
    const float* ln_g     = (const float*)d_in[9];
    const float* ln_b     = (const float*)d_in[10];
    const float* pred_w   = (const float*)d_in[11];
    const float* pred_b   = (const float*)d_in[12];
    float* out = (float*)d_out;

    float *bA, *bB, *bC, *acc;
    cudaGetSymbolAddress((void**)&bA,  g_bufA);
    cudaGetSymbolAddress((void**)&bB,  g_bufB);
    cudaGetSymbolAddress((void**)&bC,  g_bufC);
    cudaGetSymbolAddress((void**)&acc, g_acc);

    cudaFuncSetAttribute(gemm_mma_kernel<0>, cudaFuncAttributeMaxDynamicSharedMemorySize, GSMEM_B);
    cudaFuncSetAttribute(gemm_mma_kernel<1>, cudaFuncAttributeMaxDynamicSharedMemorySize, GSMEM_B);

    const int gemmGrid = (NN + 127) / 128;
    const int accN4    = NN * HH * 2 / 4;
    const int zeroGrid = (accN4 + 255) / 256;
    const int edgeGrid = (EE * 32 + 255) / 256;
    const int rowGrid  = (NN * 32 + 255) / 256;

    // encoder: h = x @ enc_w + enc_b                       -> bA
    gemm_mma_kernel<0><<<gemmGrid, 256, GSMEM_B>>>(x, FINN, nullptr, enc_w, enc_b,
                                                   nullptr, nullptr, bA, NN);

    // conv0: h = (agg(bA)+bA) @ W0 + b0                    -> bB
    zero_kernel<<<zeroGrid, 256>>>((float4*)acc, accN4);
    edge_kernel<<<edgeGrid, 256>>>(bA, src, dst, acc, EE);
    gemm_mma_kernel<1><<<gemmGrid, 256, GSMEM_B>>>(bA, HH, acc, gcn_w, gcn_b,
                                                   nullptr, nullptr, bB, NN);

    // layer 1: h2 = relu(LN(bB)) -> bA; h = conv(h2,e0)+bB -> bC  (gather deferred)
    ln_relu_kernel<<<rowGrid, 256>>>(bB, nullptr, ln_g, ln_b, bA, NN);
    zero_kernel<<<zeroGrid, 256>>>((float4*)acc, accN4);
    edge_kernel<<<edgeGrid, 256>>>(bA, src, dst, acc, EE);
    gemm_mma_kernel<1><<<gemmGrid, 256, GSMEM_B>>>(bA, HH, acc, gcn_w + HH * HH, gcn_b + HH,
                                                   bB, nullptr, bC, NN);

    // layer 2: h = bC[node_map0] (fused): h2 = relu(LN(h)) -> bB;
    //          h = conv(h2,e1) + bC[node_map0]             -> bA
    ln_relu_kernel<<<rowGrid, 256>>>(bC, node_map, ln_g + HH, ln_b + HH, bB, NN);
    zero_kernel<<<zeroGrid, 256>>>((float4*)acc, accN4);
    edge_kernel<<<edgeGrid, 256>>>(bB, src + EE, dst + EE, acc, EE);
    gemm_mma_kernel<1><<<gemmGrid, 256, GSMEM_B>>>(bB, HH, acc, gcn_w + 2 * HH * HH,
                                                   gcn_b + 2 * HH, bC, node_map, bA, NN);

    // final: rows bA[node_map1[fmap[b]]]; LN+ReLU+pred+log_softmax
    final_kernel<<<NOUTT, 128>>>(bA, node_map + NN, fmap, ln_g + 2 * HH, ln_b + 2 * HH,
                                 pred_w, pred_b, out);
}

// round 11
// speedup vs baseline: 3.0770x; 1.0865x over previous
#include <cuda_runtime.h>
#include <cuda_bf16.h>
#include <math.h>

#define NN   100000
#define EE   600000
#define FINN 256
#define HH   128
#define CC   47
#define NOUTT 10000

// ---------------- scratch (device globals; no allocations allowed) ----------
__device__ float g_bufA[(size_t)NN * HH];
__device__ float g_bufB[(size_t)NN * HH];
__device__ float g_bufC[(size_t)NN * HH];
__device__ float g_acc [(size_t)NN * HH * 2];   // interleaved {sum(w), sum(m*w)}; zero-maintained

// ======================= TF32 mma helpers ===================================
__device__ __forceinline__ unsigned f2tf32(float x) {
    unsigned r;
    asm("cvt.rna.tf32.f32 %0, %1;" : "=r"(r) : "f"(x));
    return r;
}

__device__ __forceinline__ void mma_tf32(float* d, const unsigned* a, const unsigned* b) {
    asm volatile(
        "mma.sync.aligned.m16n8k8.row.col.f32.tf32.tf32.f32 "
        "{%0,%1,%2,%3}, {%4,%5,%6,%7}, {%8,%9}, {%0,%1,%2,%3};"
        : "+f"(d[0]), "+f"(d[1]), "+f"(d[2]), "+f"(d[3])
        : "r"(a[0]), "r"(a[1]), "r"(a[2]), "r"(a[3]), "r"(b[0]), "r"(b[1]));
}

// ---------------- TF32 split GEMM, cp.async double-buffered -----------------
// C[M,128] = A[M,K] @ W[K,128] + bias (+ resid[rmap[r]])
// CTA 256 thr, tile 128x128, K chunked by 32. Raw fp32 staged via cp.async;
// tf32 hi/lo split done in registers at fragment-load time.
#define APITCH 36
#define BPITCH 136
#define A_STG (128 * APITCH)                    // floats per A stage
#define B_STG (32 * BPITCH)                     // floats per B stage
#define GSMEM_F (2 * (A_STG + B_STG))
#define GSMEM_B (GSMEM_F * 4)                   // 71680 bytes

__device__ __forceinline__ unsigned smem_u32(const void* p) {
    unsigned a;
    asm("{ .reg .u64 t; cvta.to.shared.u64 t, %1; cvt.u32.u64 %0, t; }" : "=r"(a) : "l"(p));
    return a;
}

__global__ __launch_bounds__(256, 2) void gemm_cp_kernel(
    const float* __restrict__ A, int K,
    const float* __restrict__ W,
    const float* __restrict__ bias,
    const float* __restrict__ resid,
    const int*   __restrict__ rmap,
    float* __restrict__ C, int M)
{
    extern __shared__ float smem_f[];
    const unsigned sbase = smem_u32(smem_f);

    const int tid  = threadIdx.x;
    const int wid  = tid >> 5, lane = tid & 31;
    const int wr   = wid >> 2, wc = wid & 3;      // warp 2x4 grid
    const int qid  = lane >> 2, qtr = lane & 3;   // quad row / thread-in-quad
    const int bm   = blockIdx.x * 128;

    float acc[4][4][4];
#pragma unroll
    for (int i = 0; i < 4; i++)
#pragma unroll
        for (int j = 0; j < 4; j++)
#pragma unroll
            for (int q = 0; q < 4; q++) acc[i][j][q] = 0.f;

    const int nch = K >> 5;

    // ---- async stage loader: chunk k0 -> buffer buf ----
    auto stage = [&](int k0, int buf) {
        unsigned sA = sbase + buf * (A_STG * 4);
        unsigned sB = sbase + (2 * A_STG + buf * B_STG) * 4;
#pragma unroll
        for (int j = 0; j < 4; j++) {
            int u = tid + j * 256;
            int row = u >> 3, seg = u & 7;            // 8 x 16B per A row
            unsigned sa = sA + (row * APITCH + seg * 4) * 4;
            const float* g = A + (size_t)(bm + row) * K + k0 + seg * 4;
            int sz = (bm + row < M) ? 16 : 0;
            asm volatile("cp.async.cg.shared.global [%0], [%1], 16, %2;"
                         :: "r"(sa), "l"(g), "r"(sz));
        }
#pragma unroll
        for (int j = 0; j < 4; j++) {
            int u = tid + j * 256;
            int row = u >> 5, seg = u & 31;           // 32 x 16B per B row
            unsigned sb = sB + (row * BPITCH + seg * 4) * 4;
            const float* g = W + (size_t)(k0 + row) * 128 + seg * 4;
            asm volatile("cp.async.cg.shared.global [%0], [%1], 16;"
                         :: "r"(sb), "l"(g));
        }
        asm volatile("cp.async.commit_group;");
    };

    stage(0, 0);

    for (int ch = 0; ch < nch; ch++) {
        const int cur = ch & 1;
        if (ch + 1 < nch) {
            stage((ch + 1) * 32, cur ^ 1);
            asm volatile("cp.async.wait_group 1;");
        } else {
            asm volatile("cp.async.wait_group 0;");
        }
        __syncthreads();

        const float* Ab = smem_f + cur * A_STG;
        const float* Bb = smem_f + 2 * A_STG + cur * B_STG;

#pragma unroll
        for (int ks = 0; ks < 4; ks++) {
            const int kb = ks * 8;
            unsigned ahi[4][4], alo[4][4];
#pragma unroll
            for (int mf = 0; mf < 4; mf++) {
                const float* p = Ab + (wr * 64 + mf * 16 + qid) * APITCH + kb + qtr;
                float x0 = p[0];
                float x1 = p[8 * APITCH];
                float x2 = p[4];
                float x3 = p[8 * APITCH + 4];
                ahi[mf][0] = f2tf32(x0); alo[mf][0] = f2tf32(x0 - __uint_as_float(ahi[mf][0]));
                ahi[mf][1] = f2tf32(x1); alo[mf][1] = f2tf32(x1 - __uint_as_float(ahi[mf][1]));
                ahi[mf][2] = f2tf32(x2); alo[mf][2] = f2tf32(x2 - __uint_as_float(ahi[mf][2]));
                ahi[mf][3] = f2tf32(x3); alo[mf][3] = f2tf32(x3 - __uint_as_float(ahi[mf][3]));
            }
            unsigned bhi[4][2], blo[4][2];
#pragma unroll
            for (int nf = 0; nf < 4; nf++) {
                const float* p = Bb + (kb + qtr) * BPITCH + wc * 32 + nf * 8 + qid;
                float y0 = p[0];
                float y1 = p[4 * BPITCH];
                bhi[nf][0] = f2tf32(y0); blo[nf][0] = f2tf32(y0 - __uint_as_float(bhi[nf][0]));
                bhi[nf][1] = f2tf32(y1); blo[nf][1] = f2tf32(y1 - __uint_as_float(bhi[nf][1]));
            }
#pragma unroll
            for (int mf = 0; mf < 4; mf++)
#pragma unroll
                for (int nf = 0; nf < 4; nf++) {
                    mma_tf32(acc[mf][nf], ahi[mf], bhi[nf]);
                    mma_tf32(acc[mf][nf], ahi[mf], blo[nf]);
                    mma_tf32(acc[mf][nf], alo[mf], bhi[nf]);
                }
        }
        __syncthreads();
    }

    // ---- epilogue: bias (+resid via rmap), write C ----
#pragma unroll
    for (int mf = 0; mf < 4; mf++) {
        int r0 = bm + wr * 64 + mf * 16 + qid;
        int rr0 = 0, rr1 = 0;
        if (resid) {
            if (r0 < M)     rr0 = rmap ? __ldg(rmap + r0)     : r0;
            if (r0 + 8 < M) rr1 = rmap ? __ldg(rmap + r0 + 8) : r0 + 8;
        }
#pragma unroll
        for (int nf = 0; nf < 4; nf++) {
            int c0 = wc * 32 + nf * 8 + qtr * 2;
            float2 bv = *(const float2*)&bias[c0];
            if (r0 < M) {
                float2 o;
                o.x = acc[mf][nf][0] + bv.x;
                o.y = acc[mf][nf][1] + bv.y;
                if (resid) {
                    float2 rv = *(const float2*)&resid[(size_t)rr0 * 128 + c0];
                    o.x += rv.x; o.y += rv.y;
                }
                *(float2*)&C[(size_t)r0 * 128 + c0] = o;
            }
            if (r0 + 8 < M) {
                float2 o;
                o.x = acc[mf][nf][2] + bv.x;
                o.y = acc[mf][nf][3] + bv.y;
                if (resid) {
                    float2 rv = *(const float2*)&resid[(size_t)rr1 * 128 + c0];
                    o.x += rv.x; o.y += rv.y;
                }
                *(float2*)&C[(size_t)(r0 + 8) * 128 + c0] = o;
            }
        }
    }
}

// ---------------- combine: out = acc.mw/(acc.w+eps) + h; re-zero acc --------
__global__ void combine_kernel(float* __restrict__ acc,
                               const float* __restrict__ h,
                               float* __restrict__ out, int M) {
    int i = blockIdx.x * blockDim.x + threadIdx.x;
    int n = i >> 5, f = (i & 31) * 4;
    if (n >= M) return;
    float4* ap = (float4*)(acc + (size_t)n * 256 + 2 * f);
    float4 c0 = ap[0], c1 = ap[1];
    float4 hv = *(const float4*)(h + (size_t)n * 128 + f);
    float4 o;
    o.x = c0.y / (c0.x + 1e-16f) + hv.x;
    o.y = c0.w / (c0.z + 1e-16f) + hv.y;
    o.z = c1.y / (c1.x + 1e-16f) + hv.z;
    o.w = c1.w / (c1.z + 1e-16f) + hv.w;
    *(float4*)(out + (size_t)n * 128 + f) = o;
    ap[0] = make_float4(0.f, 0.f, 0.f, 0.f);
    ap[1] = make_float4(0.f, 0.f, 0.f, 0.f);
}

// ---------------- edge pass: fused softmax num/denom via vector RED ---------
__global__ void edge_kernel(const float* __restrict__ h,
                            const int*   __restrict__ src,
                            const int*   __restrict__ dst,
                            float*       __restrict__ acc, int E) {
    int gw   = (blockIdx.x * blockDim.x + threadIdx.x) >> 5;
    int lane = threadIdx.x & 31;
    if (gw >= E) return;
    int s = __ldg(src + gw);
    int d = __ldg(dst + gw);
    float4 v = *(const float4*)&h[s * HH + lane * 4];
    float m0 = fmaxf(v.x, 0.f) + 1e-7f;
    float m1 = fmaxf(v.y, 0.f) + 1e-7f;
    float m2 = fmaxf(v.z, 0.f) + 1e-7f;
    float m3 = fmaxf(v.w, 0.f) + 1e-7f;
    float w0 = __expf(m0), w1 = __expf(m1), w2 = __expf(m2), w3 = __expf(m3);
    float* base = acc + d * (2 * HH) + lane * 8;
    asm volatile("red.global.add.v4.f32 [%0], {%1,%2,%3,%4};"
                 :: "l"(base), "f"(w0), "f"(m0 * w0), "f"(w1), "f"(m1 * w1) : "memory");
    asm volatile("red.global.add.v4.f32 [%0], {%1,%2,%3,%4};"
                 :: "l"(base + 4), "f"(w2), "f"(m2 * w2), "f"(w3), "f"(m3 * w3) : "memory");
}

// ---------------- LayerNorm + ReLU (warp per row, optional input gather) ----
__global__ void ln_relu_kernel(const float* __restrict__ in,
                               const int*   __restrict__ map,
                               const float* __restrict__ g,
                               const float* __restrict__ b,
                               float* __restrict__ out, int M) {
    int gw   = (blockIdx.x * blockDim.x + threadIdx.x) >> 5;
    int lane = threadIdx.x & 31;
    if (gw >= M) return;
    int srow = map ? __ldg(map + gw) : gw;
    float4 v = *(const float4*)&in[(size_t)srow * HH + lane * 4];
    float s = v.x + v.y + v.z + v.w;
#pragma unroll
    for (int o = 16; o; o >>= 1) s += __shfl_xor_sync(0xffffffffu, s, o);
    float mu = s * (1.f / 128.f);
    float dx = v.x - mu, dy = v.y - mu, dz = v.z - mu, dw = v.w - mu;
    float q = dx * dx + dy * dy + dz * dz + dw * dw;
#pragma unroll
    for (int o = 16; o; o >>= 1) q += __shfl_xor_sync(0xffffffffu, q, o);
    float rs = rsqrtf(q * (1.f / 128.f) + 1e-5f);
    float4 gv = *(const float4*)&g[lane * 4];
    float4 bv = *(const float4*)&b[lane * 4];
    float4 o4;
    o4.x = fmaxf(dx * rs * gv.x + bv.x, 0.f);
    o4.y = fmaxf(dy * rs * gv.y + bv.y, 0.f);
    o4.z = fmaxf(dz * rs * gv.z + bv.z, 0.f);
    o4.w = fmaxf(dw * rs * gv.w + bv.w, 0.f);
    *(float4*)&out[gw * HH + lane * 4] = o4;
}

// ---------------- final: composed gather + LN + ReLU + pred + log_softmax --
__global__ void final_kernel(const float* __restrict__ h,
                             const int*   __restrict__ nmap,
                             const int*   __restrict__ fmap,
                             const float* __restrict__ g,
                             const float* __restrict__ b,
                             const float* __restrict__ pw,
                             const float* __restrict__ pb,
                             float* __restrict__ out) {
    __shared__ float sv[128];
    __shared__ float sl[CC];
    __shared__ float red[4];
    __shared__ float stats[2];
    int t = threadIdx.x;
    int lane = t & 31, warp = t >> 5;
    int row = __ldg(nmap + __ldg(fmap + blockIdx.x));
    float x = h[(size_t)row * HH + t];
    float s = x;
#pragma unroll
    for (int o = 16; o; o >>= 1) s += __shfl_xor_sync(0xffffffffu, s, o);
    if (lane == 0) red[warp] = s;
    __syncthreads();
    float mu = (red[0] + red[1] + red[2] + red[3]) * (1.f / 128.f);
    float d = x - mu;
    float q = d * d;
#pragma unroll
    for (int o = 16; o; o >>= 1) q += __shfl_xor_sync(0xffffffffu, q, o);
    __syncthreads();
    if (lane == 0) red[warp] = q;
    __syncthreads();
    float var = (red[0] + red[1] + red[2] + red[3]) * (1.f / 128.f);
    float rs = rsqrtf(var + 1e-5f);
    sv[t] = fmaxf(d * rs * g[t] + b[t], 0.f);
    __syncthreads();
    if (t < CC) {
        float a = pb[t];
#pragma unroll 8
        for (int k = 0; k < 128; k++) a += sv[k] * pw[k * CC + t];
        sl[t] = a;
    }
    __syncthreads();
    if (t == 0) {
        float mx = -1e30f;
        for (int c = 0; c < CC; c++) mx = fmaxf(mx, sl[c]);
        float se = 0.f;
        for (int c = 0; c < CC; c++) se += expf(sl[c] - mx);
        stats[0] = mx; stats[1] = logf(se);
    }
    __syncthreads();
    if (t < CC) out[blockIdx.x * CC + t] = sl[t] - stats[0] - stats[1];
}

// ---------------- host orchestration ----------------------------------------
extern "C" void kernel_launch(void* const* d_in, const int* in_sizes, int n_in,
                              void* d_out, int out_size) {
    const float* x        = (const float*)d_in[0];
    const int*   src      = (const int*)  d_in[1];
    const int*   dst      = (const int*)  d_in[2];
    const int*   node_map = (const int*)  d_in[3];
    const int*   fmap     = (const int*)  d_in[4];
    const float* enc_w    = (const float*)d_in[5];
    const float* enc_b    = (const float*)d_in[6];
    const float* gcn_w    = (const float*)d_in[7];
    const float* gcn_b    = (const float*)d_in[8];
    const float* ln_g     = (const float*)d_in[9];
    const float* ln_b     = (const float*)d_in[10];
    const float* pred_w   = (const float*)d_in[11];
    const float* pred_b   = (const float*)d_in[12];
    float* out = (float*)d_out;

    float *bA, *bB, *bC, *acc;
    cudaGetSymbolAddress((void**)&bA,  g_bufA);
    cudaGetSymbolAddress((void**)&bB,  g_bufB);
    cudaGetSymbolAddress((void**)&bC,  g_bufC);
    cudaGetSymbolAddress((void**)&acc, g_acc);

    cudaFuncSetAttribute(gemm_cp_kernel, cudaFuncAttributeMaxDynamicSharedMemorySize, GSMEM_B);

    const int gemmGrid = (NN + 127) / 128;
    const int edgeGrid = (EE * 32 + 255) / 256;
    const int rowGrid  = (NN * 32 + 255) / 256;

    // encoder: bA = x @ enc_w + enc_b
    gemm_cp_kernel<<<gemmGrid, 256, GSMEM_B>>>(x, FINN, enc_w, enc_b,
                                               nullptr, nullptr, bA, NN);

    // conv0: acc += msgs(bA); cmb = agg + bA -> bC (acc re-zeroed); bB = cmb @ W0 + b0
    edge_kernel<<<edgeGrid, 256>>>(bA, src, dst, acc, EE);
    combine_kernel<<<rowGrid, 256>>>(acc, bA, bC, NN);
    gemm_cp_kernel<<<gemmGrid, 256, GSMEM_B>>>(bC, HH, gcn_w, gcn_b,
                                               nullptr, nullptr, bB, NN);

    // layer 1: h2 = relu(LN(bB)) -> bA; conv over edges0; out = conv + bB -> bA
    ln_relu_kernel<<<rowGrid, 256>>>(bB, nullptr, ln_g, ln_b, bA, NN);
    edge_kernel<<<edgeGrid, 256>>>(bA, src, dst, acc, EE);
    combine_kernel<<<rowGrid, 256>>>(acc, bA, bC, NN);
    gemm_cp_kernel<<<gemmGrid, 256, GSMEM_B>>>(bC, HH, gcn_w + HH * HH, gcn_b + HH,
                                               bB, nullptr, bA, NN);

    // layer 2: rows via node_map0: h2 = relu(LN(bA[map])) -> bB; conv over edges1;
    //          out = conv + bA[map] -> bB
    ln_relu_kernel<<<rowGrid, 256>>>(bA, node_map, ln_g + HH, ln_b + HH, bB, NN);
    edge_kernel<<<edgeGrid, 256>>>(bB, src + EE, dst + EE, acc, EE);
    combine_kernel<<<rowGrid, 256>>>(acc, bB, bC, NN);
    gemm_cp_kernel<<<gemmGrid, 256, GSMEM_B>>>(bC, HH, gcn_w + 2 * HH * HH, gcn_b + 2 * HH,
                                               bA, node_map, bB, NN);

    // final: rows bB[node_map1[fmap[b]]]; LN+ReLU+pred+log_softmax
    final_kernel<<<NOUTT, 128>>>(bB, node_map + NN, fmap, ln_g + 2 * HH, ln_b + 2 * HH,
                                 pred_w, pred_b, out);
}

// round 13
// speedup vs baseline: 4.5617x; 1.4825x over previous
#include <cuda_runtime.h>
#include <cuda_bf16.h>
#include <math.h>

#define NN   100000
#define EE   600000
#define FINN 256
#define HH   128
#define CC   47
#define NOUTT 10000

// ---------------- scratch (device globals; no allocations allowed) ----------
__device__ float g_bufA[(size_t)NN * HH];
__device__ float g_bufB[(size_t)NN * HH];
__device__ float g_bufC[(size_t)NN * HH];
__device__ float g_P   [(size_t)NN * HH * 2];   // per-node {w=exp(m), m*w} interleaved

// CSR scratch (2 edge sets)
#define SCHUNK 1024
#define NCHUNK ((NN + SCHUNK - 1) / SCHUNK)     // 98
__device__ int g_rs  [2][NN + 1];
__device__ int g_cur [2][NN];
__device__ int g_eidx[2][EE];
__device__ int g_S   [2][NN];
__device__ int g_bsum[2][NCHUNK];

// ======================= TF32 mma helpers ===================================
__device__ __forceinline__ unsigned f2tf32(float x) {
    unsigned r;
    asm("cvt.rna.tf32.f32 %0, %1;" : "=r"(r) : "f"(x));
    return r;
}

__device__ __forceinline__ void mma_tf32(float* d, const unsigned* a, const unsigned* b) {
    asm volatile(
        "mma.sync.aligned.m16n8k8.row.col.f32.tf32.tf32.f32 "
        "{%0,%1,%2,%3}, {%4,%5,%6,%7}, {%8,%9}, {%0,%1,%2,%3};"
        : "+f"(d[0]), "+f"(d[1]), "+f"(d[2]), "+f"(d[3])
        : "r"(a[0]), "r"(a[1]), "r"(a[2]), "r"(a[3]), "r"(b[0]), "r"(b[1]));
}

// ---------------- TF32 split GEMM, cp.async double-buffered (unchanged) -----
#define APITCH 36
#define BPITCH 136
#define A_STG (128 * APITCH)
#define B_STG (32 * BPITCH)
#define GSMEM_F (2 * (A_STG + B_STG))
#define GSMEM_B (GSMEM_F * 4)

__device__ __forceinline__ unsigned smem_u32(const void* p) {
    unsigned a;
    asm("{ .reg .u64 t; cvta.to.shared.u64 t, %1; cvt.u32.u64 %0, t; }" : "=r"(a) : "l"(p));
    return a;
}

__global__ __launch_bounds__(256, 2) void gemm_cp_kernel(
    const float* __restrict__ A, int K,
    const float* __restrict__ W,
    const float* __restrict__ bias,
    const float* __restrict__ resid,
    const int*   __restrict__ rmap,
    float* __restrict__ C, int M)
{
    extern __shared__ float smem_f[];
    const unsigned sbase = smem_u32(smem_f);

    const int tid  = threadIdx.x;
    const int wid  = tid >> 5, lane = tid & 31;
    const int wr   = wid >> 2, wc = wid & 3;
    const int qid  = lane >> 2, qtr = lane & 3;
    const int bm   = blockIdx.x * 128;

    float acc[4][4][4];
#pragma unroll
    for (int i = 0; i < 4; i++)
#pragma unroll
        for (int j = 0; j < 4; j++)
#pragma unroll
            for (int q = 0; q < 4; q++) acc[i][j][q] = 0.f;

    const int nch = K >> 5;

    auto stage = [&](int k0, int buf) {
        unsigned sA = sbase + buf * (A_STG * 4);
        unsigned sB = sbase + (2 * A_STG + buf * B_STG) * 4;
#pragma unroll
        for (int j = 0; j < 4; j++) {
            int u = tid + j * 256;
            int row = u >> 3, seg = u & 7;
            unsigned sa = sA + (row * APITCH + seg * 4) * 4;
            const float* g = A + (size_t)(bm + row) * K + k0 + seg * 4;
            int sz = (bm + row < M) ? 16 : 0;
            asm volatile("cp.async.cg.shared.global [%0], [%1], 16, %2;"
                         :: "r"(sa), "l"(g), "r"(sz));
        }
#pragma unroll
        for (int j = 0; j < 4; j++) {
            int u = tid + j * 256;
            int row = u >> 5, seg = u & 31;
            unsigned sb = sB + (row * BPITCH + seg * 4) * 4;
            const float* g = W + (size_t)(k0 + row) * 128 + seg * 4;
            asm volatile("cp.async.cg.shared.global [%0], [%1], 16;"
                         :: "r"(sb), "l"(g));
        }
        asm volatile("cp.async.commit_group;");
    };

    stage(0, 0);

    for (int ch = 0; ch < nch; ch++) {
        const int cur = ch & 1;
        if (ch + 1 < nch) {
            stage((ch + 1) * 32, cur ^ 1);
            asm volatile("cp.async.wait_group 1;");
        } else {
            asm volatile("cp.async.wait_group 0;");
        }
        __syncthreads();

        const float* Ab = smem_f + cur * A_STG;
        const float* Bb = smem_f + 2 * A_STG + cur * B_STG;

#pragma unroll
        for (int ks = 0; ks < 4; ks++) {
            const int kb = ks * 8;
            unsigned ahi[4][4], alo[4][4];
#pragma unroll
            for (int mf = 0; mf < 4; mf++) {
                const float* p = Ab + (wr * 64 + mf * 16 + qid) * APITCH + kb + qtr;
                float x0 = p[0];
                float x1 = p[8 * APITCH];
                float x2 = p[4];
                float x3 = p[8 * APITCH + 4];
                ahi[mf][0] = f2tf32(x0); alo[mf][0] = f2tf32(x0 - __uint_as_float(ahi[mf][0]));
                ahi[mf][1] = f2tf32(x1); alo[mf][1] = f2tf32(x1 - __uint_as_float(ahi[mf][1]));
                ahi[mf][2] = f2tf32(x2); alo[mf][2] = f2tf32(x2 - __uint_as_float(ahi[mf][2]));
                ahi[mf][3] = f2tf32(x3); alo[mf][3] = f2tf32(x3 - __uint_as_float(ahi[mf][3]));
            }
            unsigned bhi[4][2], blo[4][2];
#pragma unroll
            for (int nf = 0; nf < 4; nf++) {
                const float* p = Bb + (kb + qtr) * BPITCH + wc * 32 + nf * 8 + qid;
                float y0 = p[0];
                float y1 = p[4 * BPITCH];
                bhi[nf][0] = f2tf32(y0); blo[nf][0] = f2tf32(y0 - __uint_as_float(bhi[nf][0]));
                bhi[nf][1] = f2tf32(y1); blo[nf][1] = f2tf32(y1 - __uint_as_float(bhi[nf][1]));
            }
#pragma unroll
            for (int mf = 0; mf < 4; mf++)
#pragma unroll
                for (int nf = 0; nf < 4; nf++) {
                    mma_tf32(acc[mf][nf], ahi[mf], bhi[nf]);
                    mma_tf32(acc[mf][nf], ahi[mf], blo[nf]);
                    mma_tf32(acc[mf][nf], alo[mf], bhi[nf]);
                }
        }
        __syncthreads();
    }

#pragma unroll
    for (int mf = 0; mf < 4; mf++) {
        int r0 = bm + wr * 64 + mf * 16 + qid;
        int rr0 = 0, rr1 = 0;
        if (resid) {
            if (r0 < M)     rr0 = rmap ? __ldg(rmap + r0)     : r0;
            if (r0 + 8 < M) rr1 = rmap ? __ldg(rmap + r0 + 8) : r0 + 8;
        }
#pragma unroll
        for (int nf = 0; nf < 4; nf++) {
            int c0 = wc * 32 + nf * 8 + qtr * 2;
            float2 bv = *(const float2*)&bias[c0];
            if (r0 < M) {
                float2 o;
                o.x = acc[mf][nf][0] + bv.x;
                o.y = acc[mf][nf][1] + bv.y;
                if (resid) {
                    float2 rv = *(const float2*)&resid[(size_t)rr0 * 128 + c0];
                    o.x += rv.x; o.y += rv.y;
                }
                *(float2*)&C[(size_t)r0 * 128 + c0] = o;
            }
            if (r0 + 8 < M) {
                float2 o;
                o.x = acc[mf][nf][2] + bv.x;
                o.y = acc[mf][nf][3] + bv.y;
                if (resid) {
                    float2 rv = *(const float2*)&resid[(size_t)rr1 * 128 + c0];
                    o.x += rv.x; o.y += rv.y;
                }
                *(float2*)&C[(size_t)(r0 + 8) * 128 + c0] = o;
            }
        }
    }
}

// ======================= CSR build kernels ==================================
__global__ void cs_zero(int* __restrict__ a, int n) {
    int i = blockIdx.x * blockDim.x + threadIdx.x;
    if (i < n) a[i] = 0;
}

__global__ void cs_hist(const int* __restrict__ dst, int* __restrict__ cnt, int E) {
    int e = blockIdx.x * blockDim.x + threadIdx.x;
    if (e < E) atomicAdd(cnt + __ldg(dst + e), 1);
}

// per-chunk (1024 elems) inclusive scan + chunk totals
__global__ void cs_scan1(const int* __restrict__ cnt, int* __restrict__ S,
                         int* __restrict__ bsum) {
    __shared__ int sm[256];
    int c = blockIdx.x, t = threadIdx.x;
    int base = c * SCHUNK + t * 4;
    int v0 = (base + 0 < NN) ? cnt[base + 0] : 0;
    int v1 = (base + 1 < NN) ? cnt[base + 1] : 0;
    int v2 = (base + 2 < NN) ? cnt[base + 2] : 0;
    int v3 = (base + 3 < NN) ? cnt[base + 3] : 0;
    int l1 = v0 + v1, l2 = l1 + v2, l3 = l2 + v3;
    sm[t] = l3;
    __syncthreads();
    for (int off = 1; off < 256; off <<= 1) {
        int x = (t >= off) ? sm[t - off] : 0;
        __syncthreads();
        sm[t] += x;
        __syncthreads();
    }
    int excl = sm[t] - l3;
    if (base + 0 < NN) S[base + 0] = excl + v0;
    if (base + 1 < NN) S[base + 1] = excl + l1;
    if (base + 2 < NN) S[base + 2] = excl + l2;
    if (base + 3 < NN) S[base + 3] = excl + l3;
    if (t == 255) bsum[c] = sm[255];
}

// exclusive scan of chunk totals (NCHUNK <= 128)
__global__ void cs_scan2(int* __restrict__ bsum) {
    __shared__ int sm[128];
    int t = threadIdx.x;
    int v = (t < NCHUNK) ? bsum[t] : 0;
    sm[t] = v;
    __syncthreads();
    for (int off = 1; off < 128; off <<= 1) {
        int x = (t >= off) ? sm[t - off] : 0;
        __syncthreads();
        sm[t] += x;
        __syncthreads();
    }
    if (t < NCHUNK) bsum[t] = sm[t] - v;   // exclusive offsets in place
}

__global__ void cs_scan3(const int* __restrict__ S, const int* __restrict__ boff,
                         int* __restrict__ rs, int* __restrict__ cur) {
    int i = blockIdx.x * blockDim.x + threadIdx.x;
    if (i > NN) return;
    int val = (i == 0) ? 0 : S[i - 1] + boff[(i - 1) >> 10];
    rs[i] = val;
    if (i < NN) cur[i] = val;
}

__global__ void cs_scatter(const int* __restrict__ src, const int* __restrict__ dst,
                           int* __restrict__ cur, int* __restrict__ eidx, int E) {
    int e = blockIdx.x * blockDim.x + threadIdx.x;
    if (e >= E) return;
    int d = __ldg(dst + e);
    int pos = atomicAdd(cur + d, 1);
    eidx[pos] = __ldg(src + e);
}

// ---------------- prep: P[n] = {w=exp(relu(h)+eps), m*w} ---------------------
__global__ void prep_kernel(const float* __restrict__ h, float* __restrict__ P, int M) {
    int i = blockIdx.x * blockDim.x + threadIdx.x;
    int n = i >> 5, f = (i & 31) * 4;
    if (n >= M) return;
    float4 v = *(const float4*)(h + (size_t)n * 128 + f);
    float m0 = fmaxf(v.x, 0.f) + 1e-7f;
    float m1 = fmaxf(v.y, 0.f) + 1e-7f;
    float m2 = fmaxf(v.z, 0.f) + 1e-7f;
    float m3 = fmaxf(v.w, 0.f) + 1e-7f;
    float w0 = __expf(m0), w1 = __expf(m1), w2 = __expf(m2), w3 = __expf(m3);
    float4* p = (float4*)(P + (size_t)n * 256 + 2 * f);
    p[0] = make_float4(w0, m0 * w0, w1, m1 * w1);
    p[1] = make_float4(w2, m2 * w2, w3, m3 * w3);
}

// ---------------- CSR aggregation: out[d] = agg(d) + h[d] -------------------
__global__ void agg_kernel(const int* __restrict__ rs, const int* __restrict__ eidx,
                           const float* __restrict__ P, const float* __restrict__ h,
                           float* __restrict__ out) {
    int w = (blockIdx.x * blockDim.x + threadIdx.x) >> 5;
    int lane = threadIdx.x & 31;
    if (w >= NN) return;
    int beg = __ldg(rs + w), end = __ldg(rs + w + 1);
    float s0 = 0.f, t0 = 0.f, s1 = 0.f, t1 = 0.f;
    float s2 = 0.f, t2 = 0.f, s3 = 0.f, t3 = 0.f;
    for (int j = beg; j < end; j++) {
        int s = __ldg(eidx + j);
        const float4* p = (const float4*)(P + (size_t)s * 256 + lane * 8);
        float4 a = p[0], b = p[1];
        s0 += a.x; t0 += a.y; s1 += a.z; t1 += a.w;
        s2 += b.x; t2 += b.y; s3 += b.z; t3 += b.w;
    }
    float4 hv = *(const float4*)(h + (size_t)w * 128 + lane * 4);
    float4 o;
    o.x = t0 / (s0 + 1e-16f) + hv.x;
    o.y = t1 / (s1 + 1e-16f) + hv.y;
    o.z = t2 / (s2 + 1e-16f) + hv.z;
    o.w = t3 / (s3 + 1e-16f) + hv.w;
    *(float4*)(out + (size_t)w * 128 + lane * 4) = o;
}

// ---------------- LayerNorm + ReLU + P-prep (warp per row, opt gather) ------
__global__ void ln_relu_prep_kernel(const float* __restrict__ in,
                                    const int*   __restrict__ map,
                                    const float* __restrict__ g,
                                    const float* __restrict__ b,
                                    float* __restrict__ out,
                                    float* __restrict__ P, int M) {
    int gw   = (blockIdx.x * blockDim.x + threadIdx.x) >> 5;
    int lane = threadIdx.x & 31;
    if (gw >= M) return;
    int srow = map ? __ldg(map + gw) : gw;
    float4 v = *(const float4*)&in[(size_t)srow * HH + lane * 4];
    float s = v.x + v.y + v.z + v.w;
#pragma unroll
    for (int o = 16; o; o >>= 1) s += __shfl_xor_sync(0xffffffffu, s, o);
    float mu = s * (1.f / 128.f);
    float dx = v.x - mu, dy = v.y - mu, dz = v.z - mu, dw = v.w - mu;
    float q = dx * dx + dy * dy + dz * dz + dw * dw;
#pragma unroll
    for (int o = 16; o; o >>= 1) q += __shfl_xor_sync(0xffffffffu, q, o);
    float rs = rsqrtf(q * (1.f / 128.f) + 1e-5f);
    float4 gv = *(const float4*)&g[lane * 4];
    float4 bv = *(const float4*)&b[lane * 4];
    float4 o4;
    o4.x = fmaxf(dx * rs * gv.x + bv.x, 0.f);
    o4.y = fmaxf(dy * rs * gv.y + bv.y, 0.f);
    o4.z = fmaxf(dz * rs * gv.z + bv.z, 0.f);
    o4.w = fmaxf(dw * rs * gv.w + bv.w, 0.f);
    *(float4*)&out[(size_t)gw * HH + lane * 4] = o4;
    // messages from h2: h2 >= 0, so m = h2 + eps
    float m0 = o4.x + 1e-7f, m1 = o4.y + 1e-7f, m2 = o4.z + 1e-7f, m3 = o4.w + 1e-7f;
    float w0 = __expf(m0), w1 = __expf(m1), w2 = __expf(m2), w3 = __expf(m3);
    float4* pp = (float4*)(P + (size_t)gw * 256 + lane * 8);
    pp[0] = make_float4(w0, m0 * w0, w1, m1 * w1);
    pp[1] = make_float4(w2, m2 * w2, w3, m3 * w3);
}

// ---------------- final: composed gather + LN + ReLU + pred + log_softmax --
__global__ void final_kernel(const float* __restrict__ h,
                             const int*   __restrict__ nmap,
                             const int*   __restrict__ fmap,
                             const float* __restrict__ g,
                             const float* __restrict__ b,
                             const float* __restrict__ pw,
                             const float* __restrict__ pb,
                             float* __restrict__ out) {
    __shared__ float sv[128];
    __shared__ float sl[CC];
    __shared__ float red[4];
    __shared__ float stats[2];
    int t = threadIdx.x;
    int lane = t & 31, warp = t >> 5;
    int row = __ldg(nmap + __ldg(fmap + blockIdx.x));
    float x = h[(size_t)row * HH + t];
    float s = x;
#pragma unroll
    for (int o = 16; o; o >>= 1) s += __shfl_xor_sync(0xffffffffu, s, o);
    if (lane == 0) red[warp] = s;
    __syncthreads();
    float mu = (red[0] + red[1] + red[2] + red[3]) * (1.f / 128.f);
    float d = x - mu;
    float q = d * d;
#pragma unroll
    for (int o = 16; o; o >>= 1) q += __shfl_xor_sync(0xffffffffu, q, o);
    __syncthreads();
    if (lane == 0) red[warp] = q;
    __syncthreads();
    float var = (red[0] + red[1] + red[2] + red[3]) * (1.f / 128.f);
    float rs = rsqrtf(var + 1e-5f);
    sv[t] = fmaxf(d * rs * g[t] + b[t], 0.f);
    __syncthreads();
    if (t < CC) {
        float a = pb[t];
#pragma unroll 8
        for (int k = 0; k < 128; k++) a += sv[k] * pw[k * CC + t];
        sl[t] = a;
    }
    __syncthreads();
    if (t == 0) {
        float mx = -1e30f;
        for (int c = 0; c < CC; c++) mx = fmaxf(mx, sl[c]);
        float se = 0.f;
        for (int c = 0; c < CC; c++) se += expf(sl[c] - mx);
        stats[0] = mx; stats[1] = logf(se);
    }
    __syncthreads();
    if (t < CC) out[blockIdx.x * CC + t] = sl[t] - stats[0] - stats[1];
}

// ---------------- host orchestration ----------------------------------------
extern "C" void kernel_launch(void* const* d_in, const int* in_sizes, int n_in,
                              void* d_out, int out_size) {
    const float* x        = (const float*)d_in[0];
    const int*   src      = (const int*)  d_in[1];
    const int*   dst      = (const int*)  d_in[2];
    const int*   node_map = (const int*)  d_in[3];
    const int*   fmap     = (const int*)  d_in[4];
    const float* enc_w    = (const float*)d_in[5];
    const float* enc_b    = (const float*)d_in[6];
    const float* gcn_w    = (const float*)d_in[7];
    const float* gcn_b    = (const float*)d_in[8];
    const float* ln_g     = (const float*)d_in[9];
    const float* ln_b     = (const float*)d_in[10];
    const float* pred_w   = (const float*)d_in[11];
    const float* pred_b   = (const float*)d_in[12];
    float* out = (float*)d_out;

    float *bA, *bB, *bC, *P;
    int *rs, *cur, *eidx, *S, *bsum;
    cudaGetSymbolAddress((void**)&bA,   g_bufA);
    cudaGetSymbolAddress((void**)&bB,   g_bufB);
    cudaGetSymbolAddress((void**)&bC,   g_bufC);
    cudaGetSymbolAddress((void**)&P,    g_P);
    cudaGetSymbolAddress((void**)&rs,   g_rs);
    cudaGetSymbolAddress((void**)&cur,  g_cur);
    cudaGetSymbolAddress((void**)&eidx, g_eidx);
    cudaGetSymbolAddress((void**)&S,    g_S);
    cudaGetSymbolAddress((void**)&bsum, g_bsum);

    cudaFuncSetAttribute(gemm_cp_kernel, cudaFuncAttributeMaxDynamicSharedMemorySize, GSMEM_B);

    const int gemmGrid = (NN + 127) / 128;
    const int rowGrid  = (NN * 32 + 255) / 256;
    const int eGrid    = (EE + 255) / 256;
    const int nGrid1   = (NN + 1 + 255) / 256;

    // ---- CSR build for both edge sets (feature-independent) ----
    cs_zero<<<(2 * NN + 255) / 256, 256>>>(cur, 2 * NN);
    for (int b = 0; b < 2; b++) {
        cs_hist   <<<eGrid, 256>>>(dst + b * EE, cur + b * NN, EE);
        cs_scan1  <<<NCHUNK, 256>>>(cur + b * NN, S + b * NN, bsum + b * NCHUNK);
        cs_scan2  <<<1, 128>>>(bsum + b * NCHUNK);
        cs_scan3  <<<nGrid1, 256>>>(S + b * NN, bsum + b * NCHUNK,
                                    rs + b * (NN + 1), cur + b * NN);
        cs_scatter<<<eGrid, 256>>>(src + b * EE, dst + b * EE,
                                   cur + b * NN, eidx + b * EE, EE);
    }

    // encoder: bA = x @ enc_w + enc_b
    gemm_cp_kernel<<<gemmGrid, 256, GSMEM_B>>>(x, FINN, enc_w, enc_b,
                                               nullptr, nullptr, bA, NN);

    // conv0: P from bA; bC = agg(set0) + bA; bB = bC @ W0 + b0
    prep_kernel<<<rowGrid, 256>>>(bA, P, NN);
    agg_kernel<<<rowGrid, 256>>>(rs, eidx, P, bA, bC);
    gemm_cp_kernel<<<gemmGrid, 256, GSMEM_B>>>(bC, HH, gcn_w, gcn_b,
                                               nullptr, nullptr, bB, NN);

    // layer 1: h2 = relu(LN(bB)) -> bA (+P); bC = agg(set0)+bA; bA = bC@W1+b1+bB
    ln_relu_prep_kernel<<<rowGrid, 256>>>(bB, nullptr, ln_g, ln_b, bA, P, NN);
    agg_kernel<<<rowGrid, 256>>>(rs, eidx, P, bA, bC);
    gemm_cp_kernel<<<gemmGrid, 256, GSMEM_B>>>(bC, HH, gcn_w + HH * HH, gcn_b + HH,
                                               bB, nullptr, bA, NN);

    // layer 2: h2 = relu(LN(bA[map])) -> bB (+P); bC = agg(set1)+bB;
    //          bB = bC@W2+b2 + bA[map]
    ln_relu_prep_kernel<<<rowGrid, 256>>>(bA, node_map, ln_g + HH, ln_b + HH, bB, P, NN);
    agg_kernel<<<rowGrid, 256>>>(rs + (NN + 1), eidx + EE, P, bB, bC);
    gemm_cp_kernel<<<gemmGrid, 256, GSMEM_B>>>(bC, HH, gcn_w + 2 * HH * HH, gcn_b + 2 * HH,
                                               bA, node_map, bB, NN);

    // final: rows bB[node_map1[fmap[b]]]; LN+ReLU+pred+log_softmax
    final_kernel<<<NOUTT, 128>>>(bB, node_map + NN, fmap, ln_g + 2 * HH, ln_b + 2 * HH,
                                 pred_w, pred_b, out);
}

// round 14
// speedup vs baseline: 5.4036x; 1.1845x over previous
#include <cuda_runtime.h>
#include <cuda_fp16.h>
#include <math.h>

#define NN   100000
#define EE   600000
#define FINN 256
#define HH   128
#define CC   47
#define NOUTT 10000

// ---------------- scratch (device globals; no allocations allowed) ----------
__device__ float g_bufA[(size_t)NN * HH];
__device__ float g_bufB[(size_t)NN * HH];
__device__ float g_bufC[(size_t)NN * HH];
__device__ __half2 g_P[(size_t)NN * HH];        // per-node per-feature {w=exp(m), m*w}

// CSR scratch (2 edge sets)
#define SCHUNK 1024
#define NCHUNK ((NN + SCHUNK - 1) / SCHUNK)     // 98
__device__ int g_rs  [2][NN + 1];
__device__ int g_cur [2][NN];
__device__ int g_eidx[2][EE];
__device__ int g_S   [2][NN];
__device__ int g_bsum[2][NCHUNK];

// ======================= TF32 mma helpers ===================================
__device__ __forceinline__ unsigned f2tf32(float x) {
    unsigned r;
    asm("cvt.rna.tf32.f32 %0, %1;" : "=r"(r) : "f"(x));
    return r;
}

__device__ __forceinline__ void mma_tf32(float* d, const unsigned* a, const unsigned* b) {
    asm volatile(
        "mma.sync.aligned.m16n8k8.row.col.f32.tf32.tf32.f32 "
        "{%0,%1,%2,%3}, {%4,%5,%6,%7}, {%8,%9}, {%0,%1,%2,%3};"
        : "+f"(d[0]), "+f"(d[1]), "+f"(d[2]), "+f"(d[3])
        : "r"(a[0]), "r"(a[1]), "r"(a[2]), "r"(a[3]), "r"(b[0]), "r"(b[1]));
}

// ---------------- TF32 split GEMM, cp.async double-buffered -----------------
// C[M,128] = A[M,K] @ W[K,128] + bias (+ resid[rmap[r]]); optional fused
// P-prep in epilogue (Pout != null): P[r][c] = {exp(relu(o)+eps), m*exp(m)}.
#define APITCH 36
#define BPITCH 136
#define A_STG (128 * APITCH)
#define B_STG (32 * BPITCH)
#define GSMEM_F (2 * (A_STG + B_STG))
#define GSMEM_B (GSMEM_F * 4)

__device__ __forceinline__ unsigned smem_u32(const void* p) {
    unsigned a;
    asm("{ .reg .u64 t; cvta.to.shared.u64 t, %1; cvt.u32.u64 %0, t; }" : "=r"(a) : "l"(p));
    return a;
}

__global__ __launch_bounds__(256, 2) void gemm_cp_kernel(
    const float* __restrict__ A, int K,
    const float* __restrict__ W,
    const float* __restrict__ bias,
    const float* __restrict__ resid,
    const int*   __restrict__ rmap,
    float* __restrict__ C,
    __half2* __restrict__ Pout, int M)
{
    extern __shared__ float smem_f[];
    const unsigned sbase = smem_u32(smem_f);

    const int tid  = threadIdx.x;
    const int wid  = tid >> 5, lane = tid & 31;
    const int wr   = wid >> 2, wc = wid & 3;
    const int qid  = lane >> 2, qtr = lane & 3;
    const int bm   = blockIdx.x * 128;

    float acc[4][4][4];
#pragma unroll
    for (int i = 0; i < 4; i++)
#pragma unroll
        for (int j = 0; j < 4; j++)
#pragma unroll
            for (int q = 0; q < 4; q++) acc[i][j][q] = 0.f;

    const int nch = K >> 5;

    auto stage = [&](int k0, int buf) {
        unsigned sA = sbase + buf * (A_STG * 4);
        unsigned sB = sbase + (2 * A_STG + buf * B_STG) * 4;
#pragma unroll
        for (int j = 0; j < 4; j++) {
            int u = tid + j * 256;
            int row = u >> 3, seg = u & 7;
            unsigned sa = sA + (row * APITCH + seg * 4) * 4;
            const float* g = A + (size_t)(bm + row) * K + k0 + seg * 4;
            int sz = (bm + row < M) ? 16 : 0;
            asm volatile("cp.async.cg.shared.global [%0], [%1], 16, %2;"
                         :: "r"(sa), "l"(g), "r"(sz));
        }
#pragma unroll
        for (int j = 0; j < 4; j++) {
            int u = tid + j * 256;
            int row = u >> 5, seg = u & 31;
            unsigned sb = sB + (row * BPITCH + seg * 4) * 4;
            const float* g = W + (size_t)(k0 + row) * 128 + seg * 4;
            asm volatile("cp.async.cg.shared.global [%0], [%1], 16;"
                         :: "r"(sb), "l"(g));
        }
        asm volatile("cp.async.commit_group;");
    };

    stage(0, 0);

    for (int ch = 0; ch < nch; ch++) {
        const int cur = ch & 1;
        if (ch + 1 < nch) {
            stage((ch + 1) * 32, cur ^ 1);
            asm volatile("cp.async.wait_group 1;");
        } else {
            asm volatile("cp.async.wait_group 0;");
        }
        __syncthreads();

        const float* Ab = smem_f + cur * A_STG;
        const float* Bb = smem_f + 2 * A_STG + cur * B_STG;

#pragma unroll
        for (int ks = 0; ks < 4; ks++) {
            const int kb = ks * 8;
            unsigned ahi[4][4], alo[4][4];
#pragma unroll
            for (int mf = 0; mf < 4; mf++) {
                const float* p = Ab + (wr * 64 + mf * 16 + qid) * APITCH + kb + qtr;
                float x0 = p[0];
                float x1 = p[8 * APITCH];
                float x2 = p[4];
                float x3 = p[8 * APITCH + 4];
                ahi[mf][0] = f2tf32(x0); alo[mf][0] = f2tf32(x0 - __uint_as_float(ahi[mf][0]));
                ahi[mf][1] = f2tf32(x1); alo[mf][1] = f2tf32(x1 - __uint_as_float(ahi[mf][1]));
                ahi[mf][2] = f2tf32(x2); alo[mf][2] = f2tf32(x2 - __uint_as_float(ahi[mf][2]));
                ahi[mf][3] = f2tf32(x3); alo[mf][3] = f2tf32(x3 - __uint_as_float(ahi[mf][3]));
            }
            unsigned bhi[4][2], blo[4][2];
#pragma unroll
            for (int nf = 0; nf < 4; nf++) {
                const float* p = Bb + (kb + qtr) * BPITCH + wc * 32 + nf * 8 + qid;
                float y0 = p[0];
                float y1 = p[4 * BPITCH];
                bhi[nf][0] = f2tf32(y0); blo[nf][0] = f2tf32(y0 - __uint_as_float(bhi[nf][0]));
                bhi[nf][1] = f2tf32(y1); blo[nf][1] = f2tf32(y1 - __uint_as_float(bhi[nf][1]));
            }
#pragma unroll
            for (int mf = 0; mf < 4; mf++)
#pragma unroll
                for (int nf = 0; nf < 4; nf++) {
                    mma_tf32(acc[mf][nf], ahi[mf], bhi[nf]);
                    mma_tf32(acc[mf][nf], ahi[mf], blo[nf]);
                    mma_tf32(acc[mf][nf], alo[mf], bhi[nf]);
                }
        }
        __syncthreads();
    }

    // ---- epilogue: bias (+resid via rmap), write C (+ optional P-prep) ----
#pragma unroll
    for (int mf = 0; mf < 4; mf++) {
        int r0 = bm + wr * 64 + mf * 16 + qid;
        int rr0 = 0, rr1 = 0;
        if (resid) {
            if (r0 < M)     rr0 = rmap ? __ldg(rmap + r0)     : r0;
            if (r0 + 8 < M) rr1 = rmap ? __ldg(rmap + r0 + 8) : r0 + 8;
        }
#pragma unroll
        for (int nf = 0; nf < 4; nf++) {
            int c0 = wc * 32 + nf * 8 + qtr * 2;
            float2 bv = *(const float2*)&bias[c0];
            if (r0 < M) {
                float2 o;
                o.x = acc[mf][nf][0] + bv.x;
                o.y = acc[mf][nf][1] + bv.y;
                if (resid) {
                    float2 rv = *(const float2*)&resid[(size_t)rr0 * 128 + c0];
                    o.x += rv.x; o.y += rv.y;
                }
                *(float2*)&C[(size_t)r0 * 128 + c0] = o;
                if (Pout) {
                    float m0 = fmaxf(o.x, 0.f) + 1e-7f, w0 = __expf(m0);
                    float m1 = fmaxf(o.y, 0.f) + 1e-7f, w1 = __expf(m1);
                    Pout[(size_t)r0 * 128 + c0]     = __floats2half2_rn(w0, m0 * w0);
                    Pout[(size_t)r0 * 128 + c0 + 1] = __floats2half2_rn(w1, m1 * w1);
                }
            }
            if (r0 + 8 < M) {
                float2 o;
                o.x = acc[mf][nf][2] + bv.x;
                o.y = acc[mf][nf][3] + bv.y;
                if (resid) {
                    float2 rv = *(const float2*)&resid[(size_t)rr1 * 128 + c0];
                    o.x += rv.x; o.y += rv.y;
                }
                *(float2*)&C[(size_t)(r0 + 8) * 128 + c0] = o;
                if (Pout) {
                    float m0 = fmaxf(o.x, 0.f) + 1e-7f, w0 = __expf(m0);
                    float m1 = fmaxf(o.y, 0.f) + 1e-7f, w1 = __expf(m1);
                    Pout[(size_t)(r0 + 8) * 128 + c0]     = __floats2half2_rn(w0, m0 * w0);
                    Pout[(size_t)(r0 + 8) * 128 + c0 + 1] = __floats2half2_rn(w1, m1 * w1);
                }
            }
        }
    }
}

// ======================= CSR build kernels ==================================
__global__ void cs_zero(int* __restrict__ a, int n) {
    int i = blockIdx.x * blockDim.x + threadIdx.x;
    if (i < n) a[i] = 0;
}

__global__ void cs_hist(const int* __restrict__ dst, int* __restrict__ cnt, int E) {
    int e = blockIdx.x * blockDim.x + threadIdx.x;
    if (e < E) atomicAdd(cnt + __ldg(dst + e), 1);
}

__global__ void cs_scan1(const int* __restrict__ cnt, int* __restrict__ S,
                         int* __restrict__ bsum) {
    __shared__ int sm[256];
    int c = blockIdx.x, t = threadIdx.x;
    int base = c * SCHUNK + t * 4;
    int v0 = (base + 0 < NN) ? cnt[base + 0] : 0;
    int v1 = (base + 1 < NN) ? cnt[base + 1] : 0;
    int v2 = (base + 2 < NN) ? cnt[base + 2] : 0;
    int v3 = (base + 3 < NN) ? cnt[base + 3] : 0;
    int l1 = v0 + v1, l2 = l1 + v2, l3 = l2 + v3;
    sm[t] = l3;
    __syncthreads();
    for (int off = 1; off < 256; off <<= 1) {
        int x = (t >= off) ? sm[t - off] : 0;
        __syncthreads();
        sm[t] += x;
        __syncthreads();
    }
    int excl = sm[t] - l3;
    if (base + 0 < NN) S[base + 0] = excl + v0;
    if (base + 1 < NN) S[base + 1] = excl + l1;
    if (base + 2 < NN) S[base + 2] = excl + l2;
    if (base + 3 < NN) S[base + 3] = excl + l3;
    if (t == 255) bsum[c] = sm[255];
}

__global__ void cs_scan2(int* __restrict__ bsum) {
    __shared__ int sm[128];
    int t = threadIdx.x;
    int v = (t < NCHUNK) ? bsum[t] : 0;
    sm[t] = v;
    __syncthreads();
    for (int off = 1; off < 128; off <<= 1) {
        int x = (t >= off) ? sm[t - off] : 0;
        __syncthreads();
        sm[t] += x;
        __syncthreads();
    }
    if (t < NCHUNK) bsum[t] = sm[t] - v;
}

__global__ void cs_scan3(const int* __restrict__ S, const int* __restrict__ boff,
                         int* __restrict__ rs, int* __restrict__ cur) {
    int i = blockIdx.x * blockDim.x + threadIdx.x;
    if (i > NN) return;
    int val = (i == 0) ? 0 : S[i - 1] + boff[(i - 1) >> 10];
    rs[i] = val;
    if (i < NN) cur[i] = val;
}

__global__ void cs_scatter(const int* __restrict__ src, const int* __restrict__ dst,
                           int* __restrict__ cur, int* __restrict__ eidx, int E) {
    int e = blockIdx.x * blockDim.x + threadIdx.x;
    if (e >= E) return;
    int d = __ldg(dst + e);
    int pos = atomicAdd(cur + d, 1);
    eidx[pos] = __ldg(src + e);
}

// ---------------- CSR aggregation: out[d] = agg(d) + h[d] -------------------
// Warp per dst node; lane covers 4 features (one uint4 = 4 half2 per edge).
__global__ void agg_kernel(const int* __restrict__ rs, const int* __restrict__ eidx,
                           const __half2* __restrict__ P, const float* __restrict__ h,
                           float* __restrict__ out) {
    int w = (blockIdx.x * blockDim.x + threadIdx.x) >> 5;
    int lane = threadIdx.x & 31;
    if (w >= NN) return;
    int beg = __ldg(rs + w), end = __ldg(rs + w + 1);
    float s0 = 0.f, t0 = 0.f, s1 = 0.f, t1 = 0.f;
    float s2 = 0.f, t2 = 0.f, s3 = 0.f, t3 = 0.f;
    int j = beg;
    for (; j + 2 <= end; j += 2) {
        int a = __ldg(eidx + j);
        int b = __ldg(eidx + j + 1);
        uint4 pa = __ldg((const uint4*)(P + (size_t)a * 128) + lane);
        uint4 pb = __ldg((const uint4*)(P + (size_t)b * 128) + lane);
        float2 f;
        f = __half22float2(*(__half2*)&pa.x); s0 += f.x; t0 += f.y;
        f = __half22float2(*(__half2*)&pa.y); s1 += f.x; t1 += f.y;
        f = __half22float2(*(__half2*)&pa.z); s2 += f.x; t2 += f.y;
        f = __half22float2(*(__half2*)&pa.w); s3 += f.x; t3 += f.y;
        f = __half22float2(*(__half2*)&pb.x); s0 += f.x; t0 += f.y;
        f = __half22float2(*(__half2*)&pb.y); s1 += f.x; t1 += f.y;
        f = __half22float2(*(__half2*)&pb.z); s2 += f.x; t2 += f.y;
        f = __half22float2(*(__half2*)&pb.w); s3 += f.x; t3 += f.y;
    }
    if (j < end) {
        int a = __ldg(eidx + j);
        uint4 pa = __ldg((const uint4*)(P + (size_t)a * 128) + lane);
        float2 f;
        f = __half22float2(*(__half2*)&pa.x); s0 += f.x; t0 += f.y;
        f = __half22float2(*(__half2*)&pa.y); s1 += f.x; t1 += f.y;
        f = __half22float2(*(__half2*)&pa.z); s2 += f.x; t2 += f.y;
        f = __half22float2(*(__half2*)&pa.w); s3 += f.x; t3 += f.y;
    }
    float4 hv = *(const float4*)(h + (size_t)w * 128 + lane * 4);
    float4 o;
    o.x = t0 / (s0 + 1e-16f) + hv.x;
    o.y = t1 / (s1 + 1e-16f) + hv.y;
    o.z = t2 / (s2 + 1e-16f) + hv.z;
    o.w = t3 / (s3 + 1e-16f) + hv.w;
    *(float4*)(out + (size_t)w * 128 + lane * 4) = o;
}

// ---------------- LayerNorm + ReLU + P-prep (warp per row, opt gather) ------
__global__ void ln_relu_prep_kernel(const float* __restrict__ in,
                                    const int*   __restrict__ map,
                                    const float* __restrict__ g,
                                    const float* __restrict__ b,
                                    float* __restrict__ out,
                                    __half2* __restrict__ P, int M) {
    int gw   = (blockIdx.x * blockDim.x + threadIdx.x) >> 5;
    int lane = threadIdx.x & 31;
    if (gw >= M) return;
    int srow = map ? __ldg(map + gw) : gw;
    float4 v = *(const float4*)&in[(size_t)srow * HH + lane * 4];
    float s = v.x + v.y + v.z + v.w;
#pragma unroll
    for (int o = 16; o; o >>= 1) s += __shfl_xor_sync(0xffffffffu, s, o);
    float mu = s * (1.f / 128.f);
    float dx = v.x - mu, dy = v.y - mu, dz = v.z - mu, dw = v.w - mu;
    float q = dx * dx + dy * dy + dz * dz + dw * dw;
#pragma unroll
    for (int o = 16; o; o >>= 1) q += __shfl_xor_sync(0xffffffffu, q, o);
    float rs = rsqrtf(q * (1.f / 128.f) + 1e-5f);
    float4 gv = *(const float4*)&g[lane * 4];
    float4 bv = *(const float4*)&b[lane * 4];
    float4 o4;
    o4.x = fmaxf(dx * rs * gv.x + bv.x, 0.f);
    o4.y = fmaxf(dy * rs * gv.y + bv.y, 0.f);
    o4.z = fmaxf(dz * rs * gv.z + bv.z, 0.f);
    o4.w = fmaxf(dw * rs * gv.w + bv.w, 0.f);
    *(float4*)&out[(size_t)gw * HH + lane * 4] = o4;
    // h2 >= 0, so m = h2 + eps
    float m0 = o4.x + 1e-7f, m1 = o4.y + 1e-7f, m2 = o4.z + 1e-7f, m3 = o4.w + 1e-7f;
    float w0 = __expf(m0), w1 = __expf(m1), w2 = __expf(m2), w3 = __expf(m3);
    __half2 p[4];
    p[0] = __floats2half2_rn(w0, m0 * w0);
    p[1] = __floats2half2_rn(w1, m1 * w1);
    p[2] = __floats2half2_rn(w2, m2 * w2);
    p[3] = __floats2half2_rn(w3, m3 * w3);
    *(uint4*)(P + (size_t)gw * 128 + lane * 4) = *(uint4*)p;
}

// ---------------- final: composed gather + LN + ReLU + pred + log_softmax --
__global__ void final_kernel(const float* __restrict__ h,
                             const int*   __restrict__ nmap,
                             const int*   __restrict__ fmap,
                             const float* __restrict__ g,
                             const float* __restrict__ b,
                             const float* __restrict__ pw,
                             const float* __restrict__ pb,
                             float* __restrict__ out) {
    __shared__ float sv[128];
    __shared__ float sl[CC];
    __shared__ float red[4];
    __shared__ float stats[2];
    int t = threadIdx.x;
    int lane = t & 31, warp = t >> 5;
    int row = __ldg(nmap + __ldg(fmap + blockIdx.x));
    float x = h[(size_t)row * HH + t];
    float s = x;
#pragma unroll
    for (int o = 16; o; o >>= 1) s += __shfl_xor_sync(0xffffffffu, s, o);
    if (lane == 0) red[warp] = s;
    __syncthreads();
    float mu = (red[0] + red[1] + red[2] + red[3]) * (1.f / 128.f);
    float d = x - mu;
    float q = d * d;
#pragma unroll
    for (int o = 16; o; o >>= 1) q += __shfl_xor_sync(0xffffffffu, q, o);
    __syncthreads();
    if (lane == 0) red[warp] = q;
    __syncthreads();
    float var = (red[0] + red[1] + red[2] + red[3]) * (1.f / 128.f);
    float rs = rsqrtf(var + 1e-5f);
    sv[t] = fmaxf(d * rs * g[t] + b[t], 0.f);
    __syncthreads();
    if (t < CC) {
        float a = pb[t];
#pragma unroll 8
        for (int k = 0; k < 128; k++) a += sv[k] * pw[k * CC + t];
        sl[t] = a;
    }
    __syncthreads();
    if (t == 0) {
        float mx = -1e30f;
        for (int c = 0; c < CC; c++) mx = fmaxf(mx, sl[c]);
        float se = 0.f;
        for (int c = 0; c < CC; c++) se += expf(sl[c] - mx);
        stats[0] = mx; stats[1] = logf(se);
    }
    __syncthreads();
    if (t < CC) out[blockIdx.x * CC + t] = sl[t] - stats[0] - stats[1];
}

// ---------------- host orchestration ----------------------------------------
extern "C" void kernel_launch(void* const* d_in, const int* in_sizes, int n_in,
                              void* d_out, int out_size) {
    const float* x        = (const float*)d_in[0];
    const int*   src      = (const int*)  d_in[1];
    const int*   dst      = (const int*)  d_in[2];
    const int*   node_map = (const int*)  d_in[3];
    const int*   fmap     = (const int*)  d_in[4];
    const float* enc_w    = (const float*)d_in[5];
    const float* enc_b    = (const float*)d_in[6];
    const float* gcn_w    = (const float*)d_in[7];
    const float* gcn_b    = (const float*)d_in[8];
    const float* ln_g     = (const float*)d_in[9];
    const float* ln_b     = (const float*)d_in[10];
    const float* pred_w   = (const float*)d_in[11];
    const float* pred_b   = (const float*)d_in[12];
    float* out = (float*)d_out;

    float *bA, *bB, *bC;
    __half2* P;
    int *rs, *cur, *eidx, *S, *bsum;
    cudaGetSymbolAddress((void**)&bA,   g_bufA);
    cudaGetSymbolAddress((void**)&bB,   g_bufB);
    cudaGetSymbolAddress((void**)&bC,   g_bufC);
    cudaGetSymbolAddress((void**)&P,    g_P);
    cudaGetSymbolAddress((void**)&rs,   g_rs);
    cudaGetSymbolAddress((void**)&cur,  g_cur);
    cudaGetSymbolAddress((void**)&eidx, g_eidx);
    cudaGetSymbolAddress((void**)&S,    g_S);
    cudaGetSymbolAddress((void**)&bsum, g_bsum);

    cudaFuncSetAttribute(gemm_cp_kernel, cudaFuncAttributeMaxDynamicSharedMemorySize, GSMEM_B);

    const int gemmGrid = (NN + 127) / 128;
    const int rowGrid  = (NN * 32 + 255) / 256;
    const int eGrid    = (EE + 255) / 256;
    const int nGrid1   = (NN + 1 + 255) / 256;

    // ---- CSR build for both edge sets (feature-independent) ----
    cs_zero<<<(2 * NN + 255) / 256, 256>>>(cur, 2 * NN);
    for (int b = 0; b < 2; b++) {
        cs_hist   <<<eGrid, 256>>>(dst + b * EE, cur + b * NN, EE);
        cs_scan1  <<<NCHUNK, 256>>>(cur + b * NN, S + b * NN, bsum + b * NCHUNK);
        cs_scan2  <<<1, 128>>>(bsum + b * NCHUNK);
        cs_scan3  <<<nGrid1, 256>>>(S + b * NN, bsum + b * NCHUNK,
                                    rs + b * (NN + 1), cur + b * NN);
        cs_scatter<<<eGrid, 256>>>(src + b * EE, dst + b * EE,
                                   cur + b * NN, eidx + b * EE, EE);
    }

    // encoder: bA = x @ enc_w + enc_b (fused P-prep in epilogue)
    gemm_cp_kernel<<<gemmGrid, 256, GSMEM_B>>>(x, FINN, enc_w, enc_b,
                                               nullptr, nullptr, bA, P, NN);

    // conv0: bC = agg(set0) + bA; bB = bC @ W0 + b0
    agg_kernel<<<rowGrid, 256>>>(rs, eidx, P, bA, bC);
    gemm_cp_kernel<<<gemmGrid, 256, GSMEM_B>>>(bC, HH, gcn_w, gcn_b,
                                               nullptr, nullptr, bB, nullptr, NN);

    // layer 1: h2 = relu(LN(bB)) -> bA (+P); bC = agg(set0)+bA; bA = bC@W1+b1+bB
    ln_relu_prep_kernel<<<rowGrid, 256>>>(bB, nullptr, ln_g, ln_b, bA, P, NN);
    agg_kernel<<<rowGrid, 256>>>(rs, eidx, P, bA, bC);
    gemm_cp_kernel<<<gemmGrid, 256, GSMEM_B>>>(bC, HH, gcn_w + HH * HH, gcn_b + HH,
                                               bB, nullptr, bA, nullptr, NN);

    // layer 2: h2 = relu(LN(bA[map])) -> bB (+P); bC = agg(set1)+bB;
    //          bB = bC@W2+b2 + bA[map]
    ln_relu_prep_kernel<<<rowGrid, 256>>>(bA, node_map, ln_g + HH, ln_b + HH, bB, P, NN);
    agg_kernel<<<rowGrid, 256>>>(rs + (NN + 1), eidx + EE, P, bB, bC);
    gemm_cp_kernel<<<gemmGrid, 256, GSMEM_B>>>(bC, HH, gcn_w + 2 * HH * HH, gcn_b + 2 * HH,
                                               bA, node_map, bB, nullptr, NN);

    // final: rows bB[node_map1[fmap[b]]]; LN+ReLU+pred+log_softmax
    final_kernel<<<NOUTT, 128>>>(bB, node_map + NN, fmap, ln_g + 2 * HH, ln_b + 2 * HH,
                                 pred_w, pred_b, out);
}

// round 15
// speedup vs baseline: 6.0173x; 1.1136x over previous
#include <cuda_runtime.h>
#include <cuda_fp16.h>
#include <cuda_bf16.h>
#include <math.h>

#define NN   100000
#define EE   600000
#define FINN 256
#define HH   128
#define CC   47
#define NOUTT 10000

// ---------------- scratch (device globals; no allocations allowed) ----------
__device__ float g_bufA[(size_t)NN * HH];
__device__ float g_bufB[(size_t)NN * HH];
__device__ float g_bufC[(size_t)NN * HH];
__device__ __half2 g_P[(size_t)NN * HH];        // per-node per-feature {w=exp(m), m*w}

// CSR scratch (2 edge sets)
#define SCHUNK 1024
#define NCHUNK ((NN + SCHUNK - 1) / SCHUNK)     // 98
__device__ int g_rs  [2][NN + 1];
__device__ int g_cur [2][NN];
__device__ int g_eidx[2][EE];
__device__ int g_S   [2][NN];
__device__ int g_bsum[2][NCHUNK];

// ======================= bf16 split mma helpers =============================
__device__ __forceinline__ void split_bf2(float x0, float x1, unsigned& hi, unsigned& lo) {
    __nv_bfloat162 h = __floats2bfloat162_rn(x0, x1);
    float h0 = __bfloat162float(h.x), h1 = __bfloat162float(h.y);
    __nv_bfloat162 l = __floats2bfloat162_rn(x0 - h0, x1 - h1);
    hi = *(unsigned*)&h;
    lo = *(unsigned*)&l;
}

__device__ __forceinline__ void mma_bf16(float* d, const unsigned* a, const unsigned* b) {
    asm volatile(
        "mma.sync.aligned.m16n8k16.row.col.f32.bf16.bf16.f32 "
        "{%0,%1,%2,%3}, {%4,%5,%6,%7}, {%8,%9}, {%0,%1,%2,%3};"
        : "+f"(d[0]), "+f"(d[1]), "+f"(d[2]), "+f"(d[3])
        : "r"(a[0]), "r"(a[1]), "r"(a[2]), "r"(a[3]), "r"(b[0]), "r"(b[1]));
}

// ---------------- bf16 3-term split GEMM, cp.async double-buffered ----------
// C[M,128] = A[M,K] @ W[K,128] + bias (+ resid[rmap[r]]); optional fused
// P-prep in epilogue. CTA 256 thr, tile 128x128, K chunked by 32.
#define APITCH 36
#define BPITCH 132
#define A_STG (128 * APITCH)
#define B_STG (32 * BPITCH)
#define GSMEM_F (2 * (A_STG + B_STG))
#define GSMEM_B (GSMEM_F * 4)

__device__ __forceinline__ unsigned smem_u32(const void* p) {
    unsigned a;
    asm("{ .reg .u64 t; cvta.to.shared.u64 t, %1; cvt.u32.u64 %0, t; }" : "=r"(a) : "l"(p));
    return a;
}

__global__ __launch_bounds__(256, 2) void gemm_cp_kernel(
    const float* __restrict__ A, int K,
    const float* __restrict__ W,
    const float* __restrict__ bias,
    const float* __restrict__ resid,
    const int*   __restrict__ rmap,
    float* __restrict__ C,
    __half2* __restrict__ Pout, int M)
{
    extern __shared__ float smem_f[];
    const unsigned sbase = smem_u32(smem_f);

    const int tid  = threadIdx.x;
    const int wid  = tid >> 5, lane = tid & 31;
    const int wr   = wid >> 2, wc = wid & 3;
    const int qid  = lane >> 2, qtr = lane & 3;
    const int bm   = blockIdx.x * 128;

    float acc[4][4][4];
#pragma unroll
    for (int i = 0; i < 4; i++)
#pragma unroll
        for (int j = 0; j < 4; j++)
#pragma unroll
            for (int q = 0; q < 4; q++) acc[i][j][q] = 0.f;

    const int nch = K >> 5;

    auto stage = [&](int k0, int buf) {
        unsigned sA = sbase + buf * (A_STG * 4);
        unsigned sB = sbase + (2 * A_STG + buf * B_STG) * 4;
#pragma unroll
        for (int j = 0; j < 4; j++) {
            int u = tid + j * 256;
            int row = u >> 3, seg = u & 7;
            unsigned sa = sA + (row * APITCH + seg * 4) * 4;
            const float* g = A + (size_t)(bm + row) * K + k0 + seg * 4;
            int sz = (bm + row < M) ? 16 : 0;
            asm volatile("cp.async.cg.shared.global [%0], [%1], 16, %2;"
                         :: "r"(sa), "l"(g), "r"(sz));
        }
#pragma unroll
        for (int j = 0; j < 4; j++) {
            int u = tid + j * 256;
            int row = u >> 5, seg = u & 31;
            unsigned sb = sB + (row * BPITCH + seg * 4) * 4;
            const float* g = W + (size_t)(k0 + row) * 128 + seg * 4;
            asm volatile("cp.async.cg.shared.global [%0], [%1], 16;"
                         :: "r"(sb), "l"(g));
        }
        asm volatile("cp.async.commit_group;");
    };

    stage(0, 0);

    for (int ch = 0; ch < nch; ch++) {
        const int cur = ch & 1;
        if (ch + 1 < nch) {
            stage((ch + 1) * 32, cur ^ 1);
            asm volatile("cp.async.wait_group 1;");
        } else {
            asm volatile("cp.async.wait_group 0;");
        }
        __syncthreads();

        const float* Ab = smem_f + cur * A_STG;
        const float* Bb = smem_f + 2 * A_STG + cur * B_STG;

        // ---- 2 k-steps of 16 (bf16 m16n8k16, 3 split terms) ----
#pragma unroll
        for (int ks = 0; ks < 2; ks++) {
            const int kb = ks * 16;
            unsigned ah[4][4], al[4][4];
#pragma unroll
            for (int mf = 0; mf < 4; mf++) {
                const float* p = Ab + (wr * 64 + mf * 16 + qid) * APITCH + kb + 2 * qtr;
                float2 f0 = *(const float2*)p;
                float2 f1 = *(const float2*)(p + 8 * APITCH);
                float2 f2 = *(const float2*)(p + 8);
                float2 f3 = *(const float2*)(p + 8 * APITCH + 8);
                split_bf2(f0.x, f0.y, ah[mf][0], al[mf][0]);
                split_bf2(f1.x, f1.y, ah[mf][1], al[mf][1]);
                split_bf2(f2.x, f2.y, ah[mf][2], al[mf][2]);
                split_bf2(f3.x, f3.y, ah[mf][3], al[mf][3]);
            }
            unsigned bh[4][2], bl[4][2];
#pragma unroll
            for (int nf = 0; nf < 4; nf++) {
                const float* p = Bb + (kb + 2 * qtr) * BPITCH + wc * 32 + nf * 8 + qid;
                float y0 = p[0];
                float y1 = p[BPITCH];
                float y2 = p[8 * BPITCH];
                float y3 = p[9 * BPITCH];
                split_bf2(y0, y1, bh[nf][0], bl[nf][0]);
                split_bf2(y2, y3, bh[nf][1], bl[nf][1]);
            }
#pragma unroll
            for (int mf = 0; mf < 4; mf++)
#pragma unroll
                for (int nf = 0; nf < 4; nf++) {
                    mma_bf16(acc[mf][nf], ah[mf], bh[nf]);
                    mma_bf16(acc[mf][nf], ah[mf], bl[nf]);
                    mma_bf16(acc[mf][nf], al[mf], bh[nf]);
                }
        }
        __syncthreads();
    }

    // ---- epilogue: bias (+resid via rmap), write C (+ optional P-prep) ----
#pragma unroll
    for (int mf = 0; mf < 4; mf++) {
        int r0 = bm + wr * 64 + mf * 16 + qid;
        int rr0 = 0, rr1 = 0;
        if (resid) {
            if (r0 < M)     rr0 = rmap ? __ldg(rmap + r0)     : r0;
            if (r0 + 8 < M) rr1 = rmap ? __ldg(rmap + r0 + 8) : r0 + 8;
        }
#pragma unroll
        for (int nf = 0; nf < 4; nf++) {
            int c0 = wc * 32 + nf * 8 + qtr * 2;
            float2 bv = *(const float2*)&bias[c0];
            if (r0 < M) {
                float2 o;
                o.x = acc[mf][nf][0] + bv.x;
                o.y = acc[mf][nf][1] + bv.y;
                if (resid) {
                    float2 rv = *(const float2*)&resid[(size_t)rr0 * 128 + c0];
                    o.x += rv.x; o.y += rv.y;
                }
                *(float2*)&C[(size_t)r0 * 128 + c0] = o;
                if (Pout) {
                    float m0 = fmaxf(o.x, 0.f) + 1e-7f, w0 = __expf(m0);
                    float m1 = fmaxf(o.y, 0.f) + 1e-7f, w1 = __expf(m1);
                    Pout[(size_t)r0 * 128 + c0]     = __floats2half2_rn(w0, m0 * w0);
                    Pout[(size_t)r0 * 128 + c0 + 1] = __floats2half2_rn(w1, m1 * w1);
                }
            }
            if (r0 + 8 < M) {
                float2 o;
                o.x = acc[mf][nf][2] + bv.x;
                o.y = acc[mf][nf][3] + bv.y;
                if (resid) {
                    float2 rv = *(const float2*)&resid[(size_t)rr1 * 128 + c0];
                    o.x += rv.x; o.y += rv.y;
                }
                *(float2*)&C[(size_t)(r0 + 8) * 128 + c0] = o;
                if (Pout) {
                    float m0 = fmaxf(o.x, 0.f) + 1e-7f, w0 = __expf(m0);
                    float m1 = fmaxf(o.y, 0.f) + 1e-7f, w1 = __expf(m1);
                    Pout[(size_t)(r0 + 8) * 128 + c0]     = __floats2half2_rn(w0, m0 * w0);
                    Pout[(size_t)(r0 + 8) * 128 + c0 + 1] = __floats2half2_rn(w1, m1 * w1);
                }
            }
        }
    }
}

// ======================= CSR build kernels (both sets batched) ==============
__global__ void cs_zero(int* __restrict__ a, int n) {
    int i = blockIdx.x * blockDim.x + threadIdx.x;
    if (i < n) a[i] = 0;
}

// both sets: e in [0, 2E)
__global__ void cs_hist2(const int* __restrict__ dst, int* __restrict__ cnt) {
    int e = blockIdx.x * blockDim.x + threadIdx.x;
    if (e >= 2 * EE) return;
    int set = e >= EE;
    atomicAdd(cnt + set * NN + __ldg(dst + e), 1);
}

__global__ void cs_scan1_2(const int* __restrict__ cnt, int* __restrict__ S,
                           int* __restrict__ bsum) {
    __shared__ int sm[256];
    int set = blockIdx.x / NCHUNK;
    int c   = blockIdx.x % NCHUNK;
    int t = threadIdx.x;
    const int* cntS = cnt + set * NN;
    int* SS = S + set * NN;
    int base = c * SCHUNK + t * 4;
    int v0 = (base + 0 < NN) ? cntS[base + 0] : 0;
    int v1 = (base + 1 < NN) ? cntS[base + 1] : 0;
    int v2 = (base + 2 < NN) ? cntS[base + 2] : 0;
    int v3 = (base + 3 < NN) ? cntS[base + 3] : 0;
    int l1 = v0 + v1, l2 = l1 + v2, l3 = l2 + v3;
    sm[t] = l3;
    __syncthreads();
    for (int off = 1; off < 256; off <<= 1) {
        int x = (t >= off) ? sm[t - off] : 0;
        __syncthreads();
        sm[t] += x;
        __syncthreads();
    }
    int excl = sm[t] - l3;
    if (base + 0 < NN) SS[base + 0] = excl + v0;
    if (base + 1 < NN) SS[base + 1] = excl + l1;
    if (base + 2 < NN) SS[base + 2] = excl + l2;
    if (base + 3 < NN) SS[base + 3] = excl + l3;
    if (t == 255) bsum[set * NCHUNK + c] = sm[255];
}

__global__ void cs_scan2_2(int* __restrict__ bsum) {
    __shared__ int sm[128];
    int set = blockIdx.x;
    int t = threadIdx.x;
    int* bs = bsum + set * NCHUNK;
    int v = (t < NCHUNK) ? bs[t] : 0;
    sm[t] = v;
    __syncthreads();
    for (int off = 1; off < 128; off <<= 1) {
        int x = (t >= off) ? sm[t - off] : 0;
        __syncthreads();
        sm[t] += x;
        __syncthreads();
    }
    if (t < NCHUNK) bs[t] = sm[t] - v;
}

__global__ void cs_scan3_2(const int* __restrict__ S, const int* __restrict__ boff,
                           int* __restrict__ rs, int* __restrict__ cur) {
    int idx = blockIdx.x * blockDim.x + threadIdx.x;
    int set = idx / (NN + 1);
    int i   = idx % (NN + 1);
    if (set >= 2) return;
    const int* SS = S + set * NN;
    const int* bo = boff + set * NCHUNK;
    int val = (i == 0) ? 0 : SS[i - 1] + bo[(i - 1) >> 10];
    rs[set * (NN + 1) + i] = val;
    if (i < NN) cur[set * NN + i] = val;
}

__global__ void cs_scatter2(const int* __restrict__ src, const int* __restrict__ dst,
                            int* __restrict__ cur, int* __restrict__ eidx) {
    int e = blockIdx.x * blockDim.x + threadIdx.x;
    if (e >= 2 * EE) return;
    int set = e >= EE;
    int d = __ldg(dst + e);
    int pos = atomicAdd(cur + set * NN + d, 1);
    eidx[set * EE + pos] = __ldg(src + e);
}

// ---------------- CSR aggregation: out[d] = agg(d) + h[d] -------------------
__global__ void agg_kernel(const int* __restrict__ rs, const int* __restrict__ eidx,
                           const __half2* __restrict__ P, const float* __restrict__ h,
                           float* __restrict__ out) {
    int w = (blockIdx.x * blockDim.x + threadIdx.x) >> 5;
    int lane = threadIdx.x & 31;
    if (w >= NN) return;
    int beg = __ldg(rs + w), end = __ldg(rs + w + 1);
    float s0 = 0.f, t0 = 0.f, s1 = 0.f, t1 = 0.f;
    float s2 = 0.f, t2 = 0.f, s3 = 0.f, t3 = 0.f;
    int j = beg;
    for (; j + 2 <= end; j += 2) {
        int a = __ldg(eidx + j);
        int b = __ldg(eidx + j + 1);
        uint4 pa = __ldg((const uint4*)(P + (size_t)a * 128) + lane);
        uint4 pb = __ldg((const uint4*)(P + (size_t)b * 128) + lane);
        float2 f;
        f = __half22float2(*(__half2*)&pa.x); s0 += f.x; t0 += f.y;
        f = __half22float2(*(__half2*)&pa.y); s1 += f.x; t1 += f.y;
        f = __half22float2(*(__half2*)&pa.z); s2 += f.x; t2 += f.y;
        f = __half22float2(*(__half2*)&pa.w); s3 += f.x; t3 += f.y;
        f = __half22float2(*(__half2*)&pb.x); s0 += f.x; t0 += f.y;
        f = __half22float2(*(__half2*)&pb.y); s1 += f.x; t1 += f.y;
        f = __half22float2(*(__half2*)&pb.z); s2 += f.x; t2 += f.y;
        f = __half22float2(*(__half2*)&pb.w); s3 += f.x; t3 += f.y;
    }
    if (j < end) {
        int a = __ldg(eidx + j);
        uint4 pa = __ldg((const uint4*)(P + (size_t)a * 128) + lane);
        float2 f;
        f = __half22float2(*(__half2*)&pa.x); s0 += f.x; t0 += f.y;
        f = __half22float2(*(__half2*)&pa.y); s1 += f.x; t1 += f.y;
        f = __half22float2(*(__half2*)&pa.z); s2 += f.x; t2 += f.y;
        f = __half22float2(*(__half2*)&pa.w); s3 += f.x; t3 += f.y;
    }
    float4 hv = *(const float4*)(h + (size_t)w * 128 + lane * 4);
    float4 o;
    o.x = t0 / (s0 + 1e-16f) + hv.x;
    o.y = t1 / (s1 + 1e-16f) + hv.y;
    o.z = t2 / (s2 + 1e-16f) + hv.z;
    o.w = t3 / (s3 + 1e-16f) + hv.w;
    *(float4*)(out + (size_t)w * 128 + lane * 4) = o;
}

// ---------------- LayerNorm + ReLU + P-prep (warp per row, opt gather) ------
__global__ void ln_relu_prep_kernel(const float* __restrict__ in,
                                    const int*   __restrict__ map,
                                    const float* __restrict__ g,
                                    const float* __restrict__ b,
                                    float* __restrict__ out,
                                    __half2* __restrict__ P, int M) {
    int gw   = (blockIdx.x * blockDim.x + threadIdx.x) >> 5;
    int lane = threadIdx.x & 31;
    if (gw >= M) return;
    int srow = map ? __ldg(map + gw) : gw;
    float4 v = *(const float4*)&in[(size_t)srow * HH + lane * 4];
    float s = v.x + v.y + v.z + v.w;
#pragma unroll
    for (int o = 16; o; o >>= 1) s += __shfl_xor_sync(0xffffffffu, s, o);
    float mu = s * (1.f / 128.f);
    float dx = v.x - mu, dy = v.y - mu, dz = v.z - mu, dw = v.w - mu;
    float q = dx * dx + dy * dy + dz * dz + dw * dw;
#pragma unroll
    for (int o = 16; o; o >>= 1) q += __shfl_xor_sync(0xffffffffu, q, o);
    float rs = rsqrtf(q * (1.f / 128.f) + 1e-5f);
    float4 gv = *(const float4*)&g[lane * 4];
    float4 bv = *(const float4*)&b[lane * 4];
    float4 o4;
    o4.x = fmaxf(dx * rs * gv.x + bv.x, 0.f);
    o4.y = fmaxf(dy * rs * gv.y + bv.y, 0.f);
    o4.z = fmaxf(dz * rs * gv.z + bv.z, 0.f);
    o4.w = fmaxf(dw * rs * gv.w + bv.w, 0.f);
    *(float4*)&out[(size_t)gw * HH + lane * 4] = o4;
    float m0 = o4.x + 1e-7f, m1 = o4.y + 1e-7f, m2 = o4.z + 1e-7f, m3 = o4.w + 1e-7f;
    float w0 = __expf(m0), w1 = __expf(m1), w2 = __expf(m2), w3 = __expf(m3);
    __half2 p[4];
    p[0] = __floats2half2_rn(w0, m0 * w0);
    p[1] = __floats2half2_rn(w1, m1 * w1);
    p[2] = __floats2half2_rn(w2, m2 * w2);
    p[3] = __floats2half2_rn(w3, m3 * w3);
    *(uint4*)(P + (size_t)gw * 128 + lane * 4) = *(uint4*)p;
}

// ---------------- final: composed gather + LN + ReLU + pred + log_softmax --
__global__ void final_kernel(const float* __restrict__ h,
                             const int*   __restrict__ nmap,
                             const int*   __restrict__ fmap,
                             const float* __restrict__ g,
                             const float* __restrict__ b,
                             const float* __restrict__ pw,
                             const float* __restrict__ pb,
                             float* __restrict__ out) {
    __shared__ float sv[128];
    __shared__ float sl[CC];
    __shared__ float red[4];
    __shared__ float stats[2];
    int t = threadIdx.x;
    int lane = t & 31, warp = t >> 5;
    int row = __ldg(nmap + __ldg(fmap + blockIdx.x));
    float x = h[(size_t)row * HH + t];
    float s = x;
#pragma unroll
    for (int o = 16; o; o >>= 1) s += __shfl_xor_sync(0xffffffffu, s, o);
    if (lane == 0) red[warp] = s;
    __syncthreads();
    float mu = (red[0] + red[1] + red[2] + red[3]) * (1.f / 128.f);
    float d = x - mu;
    float q = d * d;
#pragma unroll
    for (int o = 16; o; o >>= 1) q += __shfl_xor_sync(0xffffffffu, q, o);
    __syncthreads();
    if (lane == 0) red[warp] = q;
    __syncthreads();
    float var = (red[0] + red[1] + red[2] + red[3]) * (1.f / 128.f);
    float rs = rsqrtf(var + 1e-5f);
    sv[t] = fmaxf(d * rs * g[t] + b[t], 0.f);
    __syncthreads();
    if (t < CC) {
        float a = pb[t];
#pragma unroll 8
        for (int k = 0; k < 128; k++) a += sv[k] * pw[k * CC + t];
        sl[t] = a;
    }
    __syncthreads();
    if (t == 0) {
        float mx = -1e30f;
        for (int c = 0; c < CC; c++) mx = fmaxf(mx, sl[c]);
        float se = 0.f;
        for (int c = 0; c < CC; c++) se += expf(sl[c] - mx);
        stats[0] = mx; stats[1] = logf(se);
    }
    __syncthreads();
    if (t < CC) out[blockIdx.x * CC + t] = sl[t] - stats[0] - stats[1];
}

// ---------------- host orchestration ----------------------------------------
extern "C" void kernel_launch(void* const* d_in, const int* in_sizes, int n_in,
                              void* d_out, int out_size) {
    const float* x        = (const float*)d_in[0];
    const int*   src      = (const int*)  d_in[1];
    const int*   dst      = (const int*)  d_in[2];
    const int*   node_map = (const int*)  d_in[3];
    const int*   fmap     = (const int*)  d_in[4];
    const float* enc_w    = (const float*)d_in[5];
    const float* enc_b    = (const float*)d_in[6];
    const float* gcn_w    = (const float*)d_in[7];
    const float* gcn_b    = (const float*)d_in[8];
    const float* ln_g     = (const float*)d_in[9];
    const float* ln_b     = (const float*)d_in[10];
    const float* pred_w   = (const float*)d_in[11];
    const float* pred_b   = (const float*)d_in[12];
    float* out = (float*)d_out;

    float *bA, *bB, *bC;
    __half2* P;
    int *rs, *cur, *eidx, *S, *bsum;
    cudaGetSymbolAddress((void**)&bA,   g_bufA);
    cudaGetSymbolAddress((void**)&bB,   g_bufB);
    cudaGetSymbolAddress((void**)&bC,   g_bufC);
    cudaGetSymbolAddress((void**)&P,    g_P);
    cudaGetSymbolAddress((void**)&rs,   g_rs);
    cudaGetSymbolAddress((void**)&cur,  g_cur);
    cudaGetSymbolAddress((void**)&eidx, g_eidx);
    cudaGetSymbolAddress((void**)&S,    g_S);
    cudaGetSymbolAddress((void**)&bsum, g_bsum);

    cudaFuncSetAttribute(gemm_cp_kernel, cudaFuncAttributeMaxDynamicSharedMemorySize, GSMEM_B);

    const int gemmGrid = (NN + 127) / 128;
    const int rowGrid  = (NN * 32 + 255) / 256;
    const int e2Grid   = (2 * EE + 255) / 256;

    // ---- CSR build for both edge sets, batched (6 launches) ----
    cs_zero    <<<(2 * NN + 255) / 256, 256>>>(cur, 2 * NN);
    cs_hist2   <<<e2Grid, 256>>>(dst, cur);
    cs_scan1_2 <<<2 * NCHUNK, 256>>>(cur, S, bsum);
    cs_scan2_2 <<<2, 128>>>(bsum);
    cs_scan3_2 <<<(2 * (NN + 1) + 255) / 256, 256>>>(S, bsum, rs, cur);
    cs_scatter2<<<e2Grid, 256>>>(src, dst, cur, eidx);

    // encoder: bA = x @ enc_w + enc_b (fused P-prep in epilogue)
    gemm_cp_kernel<<<gemmGrid, 256, GSMEM_B>>>(x, FINN, enc_w, enc_b,
                                               nullptr, nullptr, bA, P, NN);

    // conv0: bC = agg(set0) + bA; bB = bC @ W0 + b0
    agg_kernel<<<rowGrid, 256>>>(rs, eidx, P, bA, bC);
    gemm_cp_kernel<<<gemmGrid, 256, GSMEM_B>>>(bC, HH, gcn_w, gcn_b,
                                               nullptr, nullptr, bB, nullptr, NN);

    // layer 1: h2 = relu(LN(bB)) -> bA (+P); bC = agg(set0)+bA; bA = bC@W1+b1+bB
    ln_relu_prep_kernel<<<rowGrid, 256>>>(bB, nullptr, ln_g, ln_b, bA, P, NN);
    agg_kernel<<<rowGrid, 256>>>(rs, eidx, P, bA, bC);
    gemm_cp_kernel<<<gemmGrid, 256, GSMEM_B>>>(bC, HH, gcn_w + HH * HH, gcn_b + HH,
                                               bB, nullptr, bA, nullptr, NN);

    // layer 2: h2 = relu(LN(bA[map])) -> bB (+P); bC = agg(set1)+bB;
    //          bB = bC@W2+b2 + bA[map]
    ln_relu_prep_kernel<<<rowGrid, 256>>>(bA, node_map, ln_g + HH, ln_b + HH, bB, P, NN);
    agg_kernel<<<rowGrid, 256>>>(rs + (NN + 1), eidx + EE, P, bB, bC);
    gemm_cp_kernel<<<gemmGrid, 256, GSMEM_B>>>(bC, HH, gcn_w + 2 * HH * HH, gcn_b + 2 * HH,
                                               bA, node_map, bB, nullptr, NN);

    // final: rows bB[node_map1[fmap[b]]]; LN+ReLU+pred+log_softmax
    final_kernel<<<NOUTT, 128>>>(bB, node_map + NN, fmap, ln_g + 2 * HH, ln_b + 2 * HH,
                                 pred_w, pred_b, out);
}

// round 16
// speedup vs baseline: 6.6277x; 1.1014x over previous
#include <cuda_runtime.h>
#include <cuda_fp16.h>
#include <cuda_bf16.h>
#include <math.h>

#define NN   100000
#define EE   600000
#define FINN 256
#define HH   128
#define CC   47
#define NOUTT 10000

// ---------------- scratch (device globals; no allocations allowed) ----------
__device__ float g_bufA[(size_t)NN * HH];
__device__ float g_bufB[(size_t)NN * HH];
__device__ float g_bufC[(size_t)NN * HH];       // reused as split-packed A: hi[NN*64] + lo[NN*64] uints
__device__ __half2 g_P[(size_t)NN * HH];        // per-node per-feature {w=exp(m), m*w}
__device__ unsigned g_wimg[81920];              // packed bf16 hi/lo weight images

// W image offsets (uints)
#define ENC_HI 0
#define ENC_LO 16384
#define WM_HI(m) (32768 + (m) * 16384)
#define WM_LO(m) (32768 + (m) * 16384 + 8192)

// CSR scratch (2 edge sets)
#define SCHUNK 1024
#define NCHUNK ((NN + SCHUNK - 1) / SCHUNK)     // 98
__device__ int g_rs  [2][NN + 1];
__device__ int g_cur [2][NN];
__device__ int g_eidx[2][EE];
__device__ int g_S   [2][NN];
__device__ int g_bsum[2][NCHUNK];

// ======================= bf16 split mma helpers =============================
__device__ __forceinline__ void split_bf2(float x0, float x1, unsigned& hi, unsigned& lo) {
    __nv_bfloat162 h = __floats2bfloat162_rn(x0, x1);
    float h0 = __bfloat162float(h.x), h1 = __bfloat162float(h.y);
    __nv_bfloat162 l = __floats2bfloat162_rn(x0 - h0, x1 - h1);
    hi = *(unsigned*)&h;
    lo = *(unsigned*)&l;
}

__device__ __forceinline__ void mma_bf16(float* d, const unsigned* a, const unsigned* b) {
    asm volatile(
        "mma.sync.aligned.m16n8k16.row.col.f32.bf16.bf16.f32 "
        "{%0,%1,%2,%3}, {%4,%5,%6,%7}, {%8,%9}, {%0,%1,%2,%3};"
        : "+f"(d[0]), "+f"(d[1]), "+f"(d[2]), "+f"(d[3])
        : "r"(a[0]), "r"(a[1]), "r"(a[2]), "r"(a[3]), "r"(b[0]), "r"(b[1]));
}

// ---------------- weight prep: W[K,128] -> packed k-pair bf16 hi/lo ---------
// uint at [k2][n] = { bf16(W[2k2][n]) | bf16(W[2k2+1][n]) << 16 }
__global__ void prep_w_kernel(const float* __restrict__ enc_w,
                              const float* __restrict__ gcn_w,
                              unsigned* __restrict__ img) {
    int idx = blockIdx.x * blockDim.x + threadIdx.x;
    if (idx >= 40960) return;
    const float* W;
    unsigned *hi, *lo;
    int k2, n;
    if (idx < 16384) {                       // encoder: K=256 -> 128 k2-rows
        W = enc_w; k2 = idx >> 7; n = idx & 127;
        hi = img + ENC_HI; lo = img + ENC_LO;
    } else {                                 // gcn m=0..2: K=128 -> 64 k2-rows
        int t = idx - 16384;
        int m = t >> 13, r = t & 8191;
        W = gcn_w + m * 16384; k2 = r >> 7; n = r & 127;
        hi = img + WM_HI(m); lo = img + WM_LO(m);
    }
    float x0 = W[(2 * k2) * 128 + n];
    float x1 = W[(2 * k2 + 1) * 128 + n];
    unsigned h, l;
    split_bf2(x0, x1, h, l);
    hi[k2 * 128 + n] = h;
    lo[k2 * 128 + n] = l;
}

// ---------------- bf16 3-term split GEMM, cp.async double-buffered ----------
// AMODE 0: A fp32 (lda=K), split in-loop.  AMODE 1: A pre-split (Ahi/Alo packed).
// B always pre-split from weight image. C[M,128] += bias (+resid[rmap[r]]);
// optional fused P-prep in epilogue.
#define AP2 20
#define BP2 136
#define GSMEM_MAX 75776

__device__ __forceinline__ unsigned smem_u32(const void* p) {
    unsigned a;
    asm("{ .reg .u64 t; cvta.to.shared.u64 t, %1; cvt.u32.u64 %0, t; }" : "=r"(a) : "l"(p));
    return a;
}

template<int AMODE>
__global__ __launch_bounds__(256, 2) void gemm_cp_kernel(
    const float*    __restrict__ A,
    const unsigned* __restrict__ Ahi,
    const unsigned* __restrict__ Alo, int K,
    const unsigned* __restrict__ Whi,
    const unsigned* __restrict__ Wlo,
    const float* __restrict__ bias,
    const float* __restrict__ resid,
    const int*   __restrict__ rmap,
    float* __restrict__ C,
    __half2* __restrict__ Pout, int M)
{
    constexpr int ASZ = AMODE ? (2 * 128 * AP2) : (128 * 36);  // words per stage A block
    constexpr int BSZ = 2 * 16 * BP2;
    constexpr int STG = ASZ + BSZ;

    extern __shared__ unsigned smem_u[];
    const unsigned sbase = smem_u32(smem_u);

    const int tid  = threadIdx.x;
    const int wid  = tid >> 5, lane = tid & 31;
    const int wr   = wid >> 2, wc = wid & 3;
    const int qid  = lane >> 2, qtr = lane & 3;
    const int bm   = blockIdx.x * 128;

    float acc[4][4][4];
#pragma unroll
    for (int i = 0; i < 4; i++)
#pragma unroll
        for (int j = 0; j < 4; j++)
#pragma unroll
            for (int q = 0; q < 4; q++) acc[i][j][q] = 0.f;

    const int nch = K >> 5;

    auto stage = [&](int ch, int buf) {
        unsigned base = sbase + buf * (STG * 4);
        if (AMODE == 0) {
            // A fp32: 128 rows x 8 x 16B
#pragma unroll
            for (int j = 0; j < 4; j++) {
                int u = tid + j * 256;
                int row = u >> 3, seg = u & 7;
                unsigned sa = base + (row * 36 + seg * 4) * 4;
                const float* g = A + (size_t)(bm + row) * K + ch * 32 + seg * 4;
                int sz = (bm + row < M) ? 16 : 0;
                asm volatile("cp.async.cg.shared.global [%0], [%1], 16, %2;"
                             :: "r"(sa), "l"(g), "r"(sz));
            }
        } else {
            // A packed: 128 rows x 4 x 16B, hi then lo
#pragma unroll
            for (int j = 0; j < 2; j++) {
                int u = tid + j * 256;
                int row = u >> 2, seg = u & 3;
                int sz = (bm + row < M) ? 16 : 0;
                unsigned sa = base + (row * AP2 + seg * 4) * 4;
                const unsigned* gh = Ahi + (size_t)(bm + row) * 64 + ch * 16 + seg * 4;
                asm volatile("cp.async.cg.shared.global [%0], [%1], 16, %2;"
                             :: "r"(sa), "l"(gh), "r"(sz));
                unsigned sl = base + (128 * AP2 + row * AP2 + seg * 4) * 4;
                const unsigned* gl = Alo + (size_t)(bm + row) * 64 + ch * 16 + seg * 4;
                asm volatile("cp.async.cg.shared.global [%0], [%1], 16, %2;"
                             :: "r"(sl), "l"(gl), "r"(sz));
            }
        }
        // B packed: 16 k2-rows x 32 x 16B, hi then lo
#pragma unroll
        for (int j = 0; j < 2; j++) {
            int u = tid + j * 256;
            int row = u >> 5, seg = u & 31;
            unsigned sb = base + (ASZ + row * BP2 + seg * 4) * 4;
            const unsigned* gh = Whi + (size_t)(ch * 16 + row) * 128 + seg * 4;
            asm volatile("cp.async.cg.shared.global [%0], [%1], 16;"
                         :: "r"(sb), "l"(gh));
            unsigned sl = base + (ASZ + 16 * BP2 + row * BP2 + seg * 4) * 4;
            const unsigned* gl = Wlo + (size_t)(ch * 16 + row) * 128 + seg * 4;
            asm volatile("cp.async.cg.shared.global [%0], [%1], 16;"
                         :: "r"(sl), "l"(gl));
        }
        asm volatile("cp.async.commit_group;");
    };

    stage(0, 0);

    for (int ch = 0; ch < nch; ch++) {
        const int cur = ch & 1;
        if (ch + 1 < nch) {
            stage(ch + 1, cur ^ 1);
            asm volatile("cp.async.wait_group 1;");
        } else {
            asm volatile("cp.async.wait_group 0;");
        }
        __syncthreads();

        const unsigned* AhiS = smem_u + cur * STG;
        const unsigned* AloS = AhiS + 128 * AP2;
        const float*    AfS  = (const float*)(smem_u + cur * STG);
        const unsigned* BhiS = smem_u + cur * STG + ASZ;
        const unsigned* BloS = BhiS + 16 * BP2;

#pragma unroll
        for (int ks = 0; ks < 2; ks++) {
            unsigned ah[4][4], al[4][4];
#pragma unroll
            for (int mf = 0; mf < 4; mf++) {
                if (AMODE == 1) {
                    int base = (wr * 64 + mf * 16 + qid) * AP2 + ks * 8 + qtr;
                    ah[mf][0] = AhiS[base];
                    ah[mf][1] = AhiS[base + 8 * AP2];
                    ah[mf][2] = AhiS[base + 4];
                    ah[mf][3] = AhiS[base + 8 * AP2 + 4];
                    al[mf][0] = AloS[base];
                    al[mf][1] = AloS[base + 8 * AP2];
                    al[mf][2] = AloS[base + 4];
                    al[mf][3] = AloS[base + 8 * AP2 + 4];
                } else {
                    const float* p = AfS + (wr * 64 + mf * 16 + qid) * 36 + ks * 16 + 2 * qtr;
                    float2 f0 = *(const float2*)p;
                    float2 f1 = *(const float2*)(p + 8 * 36);
                    float2 f2 = *(const float2*)(p + 8);
                    float2 f3 = *(const float2*)(p + 8 * 36 + 8);
                    split_bf2(f0.x, f0.y, ah[mf][0], al[mf][0]);
                    split_bf2(f1.x, f1.y, ah[mf][1], al[mf][1]);
                    split_bf2(f2.x, f2.y, ah[mf][2], al[mf][2]);
                    split_bf2(f3.x, f3.y, ah[mf][3], al[mf][3]);
                }
            }
            unsigned bh[4][2], bl[4][2];
#pragma unroll
            for (int nf = 0; nf < 4; nf++) {
                int bw = (ks * 8 + qtr) * BP2 + wc * 32 + nf * 8 + qid;
                bh[nf][0] = BhiS[bw];
                bh[nf][1] = BhiS[bw + 4 * BP2];
                bl[nf][0] = BloS[bw];
                bl[nf][1] = BloS[bw + 4 * BP2];
            }
#pragma unroll
            for (int mf = 0; mf < 4; mf++)
#pragma unroll
                for (int nf = 0; nf < 4; nf++) {
                    mma_bf16(acc[mf][nf], ah[mf], bh[nf]);
                    mma_bf16(acc[mf][nf], ah[mf], bl[nf]);
                    mma_bf16(acc[mf][nf], al[mf], bh[nf]);
                }
        }
        __syncthreads();
    }

    // ---- epilogue: bias (+resid via rmap), write C (+ optional P-prep) ----
#pragma unroll
    for (int mf = 0; mf < 4; mf++) {
        int r0 = bm + wr * 64 + mf * 16 + qid;
        int rr0 = 0, rr1 = 0;
        if (resid) {
            if (r0 < M)     rr0 = rmap ? __ldg(rmap + r0)     : r0;
            if (r0 + 8 < M) rr1 = rmap ? __ldg(rmap + r0 + 8) : r0 + 8;
        }
#pragma unroll
        for (int nf = 0; nf < 4; nf++) {
            int c0 = wc * 32 + nf * 8 + qtr * 2;
            float2 bv = *(const float2*)&bias[c0];
            if (r0 < M) {
                float2 o;
                o.x = acc[mf][nf][0] + bv.x;
                o.y = acc[mf][nf][1] + bv.y;
                if (resid) {
                    float2 rv = *(const float2*)&resid[(size_t)rr0 * 128 + c0];
                    o.x += rv.x; o.y += rv.y;
                }
                *(float2*)&C[(size_t)r0 * 128 + c0] = o;
                if (Pout) {
                    float m0 = fmaxf(o.x, 0.f) + 1e-7f, w0 = __expf(m0);
                    float m1 = fmaxf(o.y, 0.f) + 1e-7f, w1 = __expf(m1);
                    Pout[(size_t)r0 * 128 + c0]     = __floats2half2_rn(w0, m0 * w0);
                    Pout[(size_t)r0 * 128 + c0 + 1] = __floats2half2_rn(w1, m1 * w1);
                }
            }
            if (r0 + 8 < M) {
                float2 o;
                o.x = acc[mf][nf][2] + bv.x;
                o.y = acc[mf][nf][3] + bv.y;
                if (resid) {
                    float2 rv = *(const float2*)&resid[(size_t)rr1 * 128 + c0];
                    o.x += rv.x; o.y += rv.y;
                }
                *(float2*)&C[(size_t)(r0 + 8) * 128 + c0] = o;
                if (Pout) {
                    float m0 = fmaxf(o.x, 0.f) + 1e-7f, w0 = __expf(m0);
                    float m1 = fmaxf(o.y, 0.f) + 1e-7f, w1 = __expf(m1);
                    Pout[(size_t)(r0 + 8) * 128 + c0]     = __floats2half2_rn(w0, m0 * w0);
                    Pout[(size_t)(r0 + 8) * 128 + c0 + 1] = __floats2half2_rn(w1, m1 * w1);
                }
            }
        }
    }
}

// ======================= CSR build kernels (both sets batched) ==============
__global__ void cs_zero(int* __restrict__ a, int n) {
    int i = blockIdx.x * blockDim.x + threadIdx.x;
    if (i < n) a[i] = 0;
}

__global__ void cs_hist2(const int* __restrict__ dst, int* __restrict__ cnt) {
    int e = blockIdx.x * blockDim.x + threadIdx.x;
    if (e >= 2 * EE) return;
    int set = e >= EE;
    atomicAdd(cnt + set * NN + __ldg(dst + e), 1);
}

__global__ void cs_scan1_2(const int* __restrict__ cnt, int* __restrict__ S,
                           int* __restrict__ bsum) {
    __shared__ int sm[256];
    int set = blockIdx.x / NCHUNK;
    int c   = blockIdx.x % NCHUNK;
    int t = threadIdx.x;
    const int* cntS = cnt + set * NN;
    int* SS = S + set * NN;
    int base = c * SCHUNK + t * 4;
    int v0 = (base + 0 < NN) ? cntS[base + 0] : 0;
    int v1 = (base + 1 < NN) ? cntS[base + 1] : 0;
    int v2 = (base + 2 < NN) ? cntS[base + 2] : 0;
    int v3 = (base + 3 < NN) ? cntS[base + 3] : 0;
    int l1 = v0 + v1, l2 = l1 + v2, l3 = l2 + v3;
    sm[t] = l3;
    __syncthreads();
    for (int off = 1; off < 256; off <<= 1) {
        int x = (t >= off) ? sm[t - off] : 0;
        __syncthreads();
        sm[t] += x;
        __syncthreads();
    }
    int excl = sm[t] - l3;
    if (base + 0 < NN) SS[base + 0] = excl + v0;
    if (base + 1 < NN) SS[base + 1] = excl + l1;
    if (base + 2 < NN) SS[base + 2] = excl + l2;
    if (base + 3 < NN) SS[base + 3] = excl + l3;
    if (t == 255) bsum[set * NCHUNK + c] = sm[255];
}

__global__ void cs_scan2_2(int* __restrict__ bsum) {
    __shared__ int sm[128];
    int set = blockIdx.x;
    int t = threadIdx.x;
    int* bs = bsum + set * NCHUNK;
    int v = (t < NCHUNK) ? bs[t] : 0;
    sm[t] = v;
    __syncthreads();
    for (int off = 1; off < 128; off <<= 1) {
        int x = (t >= off) ? sm[t - off] : 0;
        __syncthreads();
        sm[t] += x;
        __syncthreads();
    }
    if (t < NCHUNK) bs[t] = sm[t] - v;
}

__global__ void cs_scan3_2(const int* __restrict__ S, const int* __restrict__ boff,
                           int* __restrict__ rs, int* __restrict__ cur) {
    int idx = blockIdx.x * blockDim.x + threadIdx.x;
    int set = idx / (NN + 1);
    int i   = idx % (NN + 1);
    if (set >= 2) return;
    const int* SS = S + set * NN;
    const int* bo = boff + set * NCHUNK;
    int val = (i == 0) ? 0 : SS[i - 1] + bo[(i - 1) >> 10];
    rs[set * (NN + 1) + i] = val;
    if (i < NN) cur[set * NN + i] = val;
}

__global__ void cs_scatter2(const int* __restrict__ src, const int* __restrict__ dst,
                            int* __restrict__ cur, int* __restrict__ eidx) {
    int e = blockIdx.x * blockDim.x + threadIdx.x;
    if (e >= 2 * EE) return;
    int set = e >= EE;
    int d = __ldg(dst + e);
    int pos = atomicAdd(cur + set * NN + d, 1);
    eidx[set * EE + pos] = __ldg(src + e);
}

// ---------------- CSR aggregation: split-packed out = agg(d) + h[d] ---------
__global__ void agg_kernel(const int* __restrict__ rs, const int* __restrict__ eidx,
                           const __half2* __restrict__ P, const float* __restrict__ h,
                           unsigned* __restrict__ outhi, unsigned* __restrict__ outlo) {
    int w = (blockIdx.x * blockDim.x + threadIdx.x) >> 5;
    int lane = threadIdx.x & 31;
    if (w >= NN) return;
    int beg = __ldg(rs + w), end = __ldg(rs + w + 1);
    float s0 = 0.f, t0 = 0.f, s1 = 0.f, t1 = 0.f;
    float s2 = 0.f, t2 = 0.f, s3 = 0.f, t3 = 0.f;
    int j = beg;
    for (; j + 2 <= end; j += 2) {
        int a = __ldg(eidx + j);
        int b = __ldg(eidx + j + 1);
        uint4 pa = __ldg((const uint4*)(P + (size_t)a * 128) + lane);
        uint4 pb = __ldg((const uint4*)(P + (size_t)b * 128) + lane);
        float2 f;
        f = __half22float2(*(__half2*)&pa.x); s0 += f.x; t0 += f.y;
        f = __half22float2(*(__half2*)&pa.y); s1 += f.x; t1 += f.y;
        f = __half22float2(*(__half2*)&pa.z); s2 += f.x; t2 += f.y;
        f = __half22float2(*(__half2*)&pa.w); s3 += f.x; t3 += f.y;
        f = __half22float2(*(__half2*)&pb.x); s0 += f.x; t0 += f.y;
        f = __half22float2(*(__half2*)&pb.y); s1 += f.x; t1 += f.y;
        f = __half22float2(*(__half2*)&pb.z); s2 += f.x; t2 += f.y;
        f = __half22float2(*(__half2*)&pb.w); s3 += f.x; t3 += f.y;
    }
    if (j < end) {
        int a = __ldg(eidx + j);
        uint4 pa = __ldg((const uint4*)(P + (size_t)a * 128) + lane);
        float2 f;
        f = __half22float2(*(__half2*)&pa.x); s0 += f.x; t0 += f.y;
        f = __half22float2(*(__half2*)&pa.y); s1 += f.x; t1 += f.y;
        f = __half22float2(*(__half2*)&pa.z); s2 += f.x; t2 += f.y;
        f = __half22float2(*(__half2*)&pa.w); s3 += f.x; t3 += f.y;
    }
    float4 hv = *(const float4*)(h + (size_t)w * 128 + lane * 4);
    float o0 = t0 / (s0 + 1e-16f) + hv.x;
    float o1 = t1 / (s1 + 1e-16f) + hv.y;
    float o2 = t2 / (s2 + 1e-16f) + hv.z;
    float o3 = t3 / (s3 + 1e-16f) + hv.w;
    uint2 hv2, lv2;
    split_bf2(o0, o1, hv2.x, lv2.x);
    split_bf2(o2, o3, hv2.y, lv2.y);
    *(uint2*)(outhi + (size_t)w * 64 + lane * 2) = hv2;
    *(uint2*)(outlo + (size_t)w * 64 + lane * 2) = lv2;
}

// ---------------- LayerNorm + ReLU + P-prep (warp per row, opt gather) ------
__global__ void ln_relu_prep_kernel(const float* __restrict__ in,
                                    const int*   __restrict__ map,
                                    const float* __restrict__ g,
                                    const float* __restrict__ b,
                                    float* __restrict__ out,
                                    __half2* __restrict__ P, int M) {
    int gw   = (blockIdx.x * blockDim.x + threadIdx.x) >> 5;
    int lane = threadIdx.x & 31;
    if (gw >= M) return;
    int srow = map ? __ldg(map + gw) : gw;
    float4 v = *(const float4*)&in[(size_t)srow * HH + lane * 4];
    float s = v.x + v.y + v.z + v.w;
#pragma unroll
    for (int o = 16; o; o >>= 1) s += __shfl_xor_sync(0xffffffffu, s, o);
    float mu = s * (1.f / 128.f);
    float dx = v.x - mu, dy = v.y - mu, dz = v.z - mu, dw = v.w - mu;
    float q = dx * dx + dy * dy + dz * dz + dw * dw;
#pragma unroll
    for (int o = 16; o; o >>= 1) q += __shfl_xor_sync(0xffffffffu, q, o);
    float rs = rsqrtf(q * (1.f / 128.f) + 1e-5f);
    float4 gv = *(const float4*)&g[lane * 4];
    float4 bv = *(const float4*)&b[lane * 4];
    float4 o4;
    o4.x = fmaxf(dx * rs * gv.x + bv.x, 0.f);
    o4.y = fmaxf(dy * rs * gv.y + bv.y, 0.f);
    o4.z = fmaxf(dz * rs * gv.z + bv.z, 0.f);
    o4.w = fmaxf(dw * rs * gv.w + bv.w, 0.f);
    *(float4*)&out[(size_t)gw * HH + lane * 4] = o4;
    float m0 = o4.x + 1e-7f, m1 = o4.y + 1e-7f, m2 = o4.z + 1e-7f, m3 = o4.w + 1e-7f;
    float w0 = __expf(m0), w1 = __expf(m1), w2 = __expf(m2), w3 = __expf(m3);
    __half2 p[4];
    p[0] = __floats2half2_rn(w0, m0 * w0);
    p[1] = __floats2half2_rn(w1, m1 * w1);
    p[2] = __floats2half2_rn(w2, m2 * w2);
    p[3] = __floats2half2_rn(w3, m3 * w3);
    *(uint4*)(P + (size_t)gw * 128 + lane * 4) = *(uint4*)p;
}

// ---------------- final: composed gather + LN + ReLU + pred + log_softmax --
__global__ void final_kernel(const float* __restrict__ h,
                             const int*   __restrict__ nmap,
                             const int*   __restrict__ fmap,
                             const float* __restrict__ g,
                             const float* __restrict__ b,
                             const float* __restrict__ pw,
                             const float* __restrict__ pb,
                             float* __restrict__ out) {
    __shared__ float sv[128];
    __shared__ float sl[CC];
    __shared__ float red[4];
    __shared__ float stats[2];
    int t = threadIdx.x;
    int lane = t & 31, warp = t >> 5;
    int row = __ldg(nmap + __ldg(fmap + blockIdx.x));
    float x = h[(size_t)row * HH + t];
    float s = x;
#pragma unroll
    for (int o = 16; o; o >>= 1) s += __shfl_xor_sync(0xffffffffu, s, o);
    if (lane == 0) red[warp] = s;
    __syncthreads();
    float mu = (red[0] + red[1] + red[2] + red[3]) * (1.f / 128.f);
    float d = x - mu;
    float q = d * d;
#pragma unroll
    for (int o = 16; o; o >>= 1) q += __shfl_xor_sync(0xffffffffu, q, o);
    __syncthreads();
    if (lane == 0) red[warp] = q;
    __syncthreads();
    float var = (red[0] + red[1] + red[2] + red[3]) * (1.f / 128.f);
    float rs = rsqrtf(var + 1e-5f);
    sv[t] = fmaxf(d * rs * g[t] + b[t], 0.f);
    __syncthreads();
    if (t < CC) {
        float a = pb[t];
#pragma unroll 8
        for (int k = 0; k < 128; k++) a += sv[k] * pw[k * CC + t];
        sl[t] = a;
    }
    __syncthreads();
    if (t == 0) {
        float mx = -1e30f;
        for (int c = 0; c < CC; c++) mx = fmaxf(mx, sl[c]);
        float se = 0.f;
        for (int c = 0; c < CC; c++) se += expf(sl[c] - mx);
        stats[0] = mx; stats[1] = logf(se);
    }
    __syncthreads();
    if (t < CC) out[blockIdx.x * CC + t] = sl[t] - stats[0] - stats[1];
}

// ---------------- host orchestration ----------------------------------------
extern "C" void kernel_launch(void* const* d_in, const int* in_sizes, int n_in,
                              void* d_out, int out_size) {
    const float* x        = (const float*)d_in[0];
    const int*   src      = (const int*)  d_in[1];
    const int*   dst      = (const int*)  d_in[2];
    const int*   node_map = (const int*)  d_in[3];
    const int*   fmap     = (const int*)  d_in[4];
    const float* enc_w    = (const float*)d_in[5];
    const float* enc_b    = (const float*)d_in[6];
    const float* gcn_w    = (const float*)d_in[7];
    const float* gcn_b    = (const float*)d_in[8];
    const float* ln_g     = (const float*)d_in[9];
    const float* ln_b     = (const float*)d_in[10];
    const float* pred_w   = (const float*)d_in[11];
    const float* pred_b   = (const float*)d_in[12];
    float* out = (float*)d_out;

    float *bA, *bB, *bC;
    __half2* P;
    unsigned* wimg;
    int *rs, *cur, *eidx, *S, *bsum;
    cudaGetSymbolAddress((void**)&bA,   g_bufA);
    cudaGetSymbolAddress((void**)&bB,   g_bufB);
    cudaGetSymbolAddress((void**)&bC,   g_bufC);
    cudaGetSymbolAddress((void**)&P,    g_P);
    cudaGetSymbolAddress((void**)&wimg, g_wimg);
    cudaGetSymbolAddress((void**)&rs,   g_rs);
    cudaGetSymbolAddress((void**)&cur,  g_cur);
    cudaGetSymbolAddress((void**)&eidx, g_eidx);
    cudaGetSymbolAddress((void**)&S,    g_S);
    cudaGetSymbolAddress((void**)&bsum, g_bsum);

    unsigned* bChi = (unsigned*)bC;                 // packed A for conv GEMMs
    unsigned* bClo = bChi + (size_t)NN * 64;

    cudaFuncSetAttribute(gemm_cp_kernel<0>, cudaFuncAttributeMaxDynamicSharedMemorySize, GSMEM_MAX);
    cudaFuncSetAttribute(gemm_cp_kernel<1>, cudaFuncAttributeMaxDynamicSharedMemorySize, GSMEM_MAX);

    const int gemmGrid = (NN + 127) / 128;
    const int rowGrid  = (NN * 32 + 255) / 256;
    const int e2Grid   = (2 * EE + 255) / 256;

    // weight split (once per call)
    prep_w_kernel<<<(40960 + 255) / 256, 256>>>(enc_w, gcn_w, wimg);

    // ---- CSR build for both edge sets, batched ----
    cs_zero    <<<(2 * NN + 255) / 256, 256>>>(cur, 2 * NN);
    cs_hist2   <<<e2Grid, 256>>>(dst, cur);
    cs_scan1_2 <<<2 * NCHUNK, 256>>>(cur, S, bsum);
    cs_scan2_2 <<<2, 128>>>(bsum);
    cs_scan3_2 <<<(2 * (NN + 1) + 255) / 256, 256>>>(S, bsum, rs, cur);
    cs_scatter2<<<e2Grid, 256>>>(src, dst, cur, eidx);

    // encoder: bA = x @ enc_w + enc_b (fused P-prep)
    gemm_cp_kernel<0><<<gemmGrid, 256, GSMEM_MAX>>>(
        x, nullptr, nullptr, FINN, wimg + ENC_HI, wimg + ENC_LO,
        enc_b, nullptr, nullptr, bA, P, NN);

    // conv0: split-packed bC = agg(set0) + bA; bB = bC @ W0 + b0
    agg_kernel<<<rowGrid, 256>>>(rs, eidx, P, bA, bChi, bClo);
    gemm_cp_kernel<1><<<gemmGrid, 256, GSMEM_MAX>>>(
        nullptr, bChi, bClo, HH, wimg + WM_HI(0), wimg + WM_LO(0),
        gcn_b, nullptr, nullptr, bB, nullptr, NN);

    // layer 1: h2 = relu(LN(bB)) -> bA (+P); bC = agg(set0)+bA; bA = bC@W1+b1+bB
    ln_relu_prep_kernel<<<rowGrid, 256>>>(bB, nullptr, ln_g, ln_b, bA, P, NN);
    agg_kernel<<<rowGrid, 256>>>(rs, eidx, P, bA, bChi, bClo);
    gemm_cp_kernel<1><<<gemmGrid, 256, GSMEM_MAX>>>(
        nullptr, bChi, bClo, HH, wimg + WM_HI(1), wimg + WM_LO(1),
        gcn_b + HH, bB, nullptr, bA, nullptr, NN);

    // layer 2: h2 = relu(LN(bA[map])) -> bB (+P); bC = agg(set1)+bB;
    //          bB = bC@W2+b2 + bA[map]
    ln_relu_prep_kernel<<<rowGrid, 256>>>(bA, node_map, ln_g + HH, ln_b + HH, bB, P, NN);
    agg_kernel<<<rowGrid, 256>>>(rs + (NN + 1), eidx + EE, P, bB, bChi, bClo);
    gemm_cp_kernel<1><<<gemmGrid, 256, GSMEM_MAX>>>(
        nullptr, bChi, bClo, HH, wimg + WM_HI(2), wimg + WM_LO(2),
        gcn_b + 2 * HH, bA, node_map, bB, nullptr, NN);

    // final: rows bB[node_map1[fmap[b]]]; LN+ReLU+pred+log_softmax
    final_kernel<<<NOUTT, 128>>>(bB, node_map + NN, fmap, ln_g + 2 * HH, ln_b + 2 * HH,
                                 pred_w, pred_b, out);
}

// round 17
// speedup vs baseline: 7.3987x; 1.1163x over previous
#include <cuda_runtime.h>
#include <cuda_fp16.h>
#include <cuda_bf16.h>
#include <math.h>

#define NN   100000
#define EE   600000
#define FINN 256
#define HH   128
#define CC   47
#define NOUTT 10000

// ---------------- scratch (device globals; no allocations allowed) ----------
__device__ float g_bufA[(size_t)NN * HH];
__device__ float g_bufB[(size_t)NN * HH];
__device__ float g_bufC[(size_t)NN * HH];       // reused as split-packed A: hi[NN*64] + lo[NN*64] uints
__device__ __half2 g_P[(size_t)NN * HH];        // per-node per-feature {w=exp(m), m*w}
__device__ unsigned g_wimg[81920];              // packed bf16 hi/lo weight images
__device__ int g_cmap[2][NOUTT];                // [0]=dst row (moved), [1]=resid row (pre-move)

// W image offsets (uints)
#define ENC_HI 0
#define ENC_LO 16384
#define WM_HI(m) (32768 + (m) * 16384)
#define WM_LO(m) (32768 + (m) * 16384 + 8192)

// CSR scratch (2 edge sets)
#define SCHUNK 1024
#define NCHUNK ((NN + SCHUNK - 1) / SCHUNK)     // 98
__device__ int g_rs  [2][NN + 1];
__device__ int g_cur [2][NN];
__device__ int g_eidx[2][EE];
__device__ int g_S   [2][NN];
__device__ int g_bsum[2][NCHUNK];

// ======================= bf16 split mma helpers =============================
__device__ __forceinline__ void split_bf2(float x0, float x1, unsigned& hi, unsigned& lo) {
    __nv_bfloat162 h = __floats2bfloat162_rn(x0, x1);
    float h0 = __bfloat162float(h.x), h1 = __bfloat162float(h.y);
    __nv_bfloat162 l = __floats2bfloat162_rn(x0 - h0, x1 - h1);
    hi = *(unsigned*)&h;
    lo = *(unsigned*)&l;
}

__device__ __forceinline__ void mma_bf16(float* d, const unsigned* a, const unsigned* b) {
    asm volatile(
        "mma.sync.aligned.m16n8k16.row.col.f32.bf16.bf16.f32 "
        "{%0,%1,%2,%3}, {%4,%5,%6,%7}, {%8,%9}, {%0,%1,%2,%3};"
        : "+f"(d[0]), "+f"(d[1]), "+f"(d[2]), "+f"(d[3])
        : "r"(a[0]), "r"(a[1]), "r"(a[2]), "r"(a[3]), "r"(b[0]), "r"(b[1]));
}

// ---------------- weight prep: W[K,128] -> packed k-pair bf16 hi/lo ---------
__global__ void prep_w_kernel(const float* __restrict__ enc_w,
                              const float* __restrict__ gcn_w,
                              unsigned* __restrict__ img) {
    int idx = blockIdx.x * blockDim.x + threadIdx.x;
    if (idx >= 40960) return;
    const float* W;
    unsigned *hi, *lo;
    int k2, n;
    if (idx < 16384) {
        W = enc_w; k2 = idx >> 7; n = idx & 127;
        hi = img + ENC_HI; lo = img + ENC_LO;
    } else {
        int t = idx - 16384;
        int m = t >> 13, r = t & 8191;
        W = gcn_w + m * 16384; k2 = r >> 7; n = r & 127;
        hi = img + WM_HI(m); lo = img + WM_LO(m);
    }
    float x0 = W[(2 * k2) * 128 + n];
    float x1 = W[(2 * k2 + 1) * 128 + n];
    unsigned h, l;
    split_bf2(x0, x1, h, l);
    hi[k2 * 128 + n] = h;
    lo[k2 * 128 + n] = l;
}

// ---------------- map composition for layer-2 compaction --------------------
__global__ void compose_map_kernel(const int* __restrict__ node_map,
                                   const int* __restrict__ fmap,
                                   int* __restrict__ cdst, int* __restrict__ cres) {
    int b = blockIdx.x * blockDim.x + threadIdx.x;
    if (b >= NOUTT) return;
    int rb = __ldg(node_map + NN + __ldg(fmap + b));   // node_map1[fmap[b]]
    cdst[b] = rb;
    cres[b] = __ldg(node_map + rb);                    // node_map0[rb]
}

// ---------------- bf16 3-term split GEMM, cp.async double-buffered ----------
#define AP2 20
#define BP2 136
#define GSMEM_MAX 75776

__device__ __forceinline__ unsigned smem_u32(const void* p) {
    unsigned a;
    asm("{ .reg .u64 t; cvta.to.shared.u64 t, %1; cvt.u32.u64 %0, t; }" : "=r"(a) : "l"(p));
    return a;
}

template<int AMODE>
__global__ __launch_bounds__(256, 2) void gemm_cp_kernel(
    const float*    __restrict__ A,
    const unsigned* __restrict__ Ahi,
    const unsigned* __restrict__ Alo, int K,
    const unsigned* __restrict__ Whi,
    const unsigned* __restrict__ Wlo,
    const float* __restrict__ bias,
    const float* __restrict__ resid,
    const int*   __restrict__ rmap,
    float* __restrict__ C,
    __half2* __restrict__ Pout, int M)
{
    constexpr int ASZ = AMODE ? (2 * 128 * AP2) : (128 * 36);
    constexpr int BSZ = 2 * 16 * BP2;
    constexpr int STG = ASZ + BSZ;

    extern __shared__ unsigned smem_u[];
    const unsigned sbase = smem_u32(smem_u);

    const int tid  = threadIdx.x;
    const int wid  = tid >> 5, lane = tid & 31;
    const int wr   = wid >> 2, wc = wid & 3;
    const int qid  = lane >> 2, qtr = lane & 3;
    const int bm   = blockIdx.x * 128;

    float acc[4][4][4];
#pragma unroll
    for (int i = 0; i < 4; i++)
#pragma unroll
        for (int j = 0; j < 4; j++)
#pragma unroll
            for (int q = 0; q < 4; q++) acc[i][j][q] = 0.f;

    const int nch = K >> 5;

    auto stage = [&](int ch, int buf) {
        unsigned base = sbase + buf * (STG * 4);
        if (AMODE == 0) {
#pragma unroll
            for (int j = 0; j < 4; j++) {
                int u = tid + j * 256;
                int row = u >> 3, seg = u & 7;
                unsigned sa = base + (row * 36 + seg * 4) * 4;
                const float* g = A + (size_t)(bm + row) * K + ch * 32 + seg * 4;
                int sz = (bm + row < M) ? 16 : 0;
                asm volatile("cp.async.cg.shared.global [%0], [%1], 16, %2;"
                             :: "r"(sa), "l"(g), "r"(sz));
            }
        } else {
#pragma unroll
            for (int j = 0; j < 2; j++) {
                int u = tid + j * 256;
                int row = u >> 2, seg = u & 3;
                int sz = (bm + row < M) ? 16 : 0;
                unsigned sa = base + (row * AP2 + seg * 4) * 4;
                const unsigned* gh = Ahi + (size_t)(bm + row) * 64 + ch * 16 + seg * 4;
                asm volatile("cp.async.cg.shared.global [%0], [%1], 16, %2;"
                             :: "r"(sa), "l"(gh), "r"(sz));
                unsigned sl = base + (128 * AP2 + row * AP2 + seg * 4) * 4;
                const unsigned* gl = Alo + (size_t)(bm + row) * 64 + ch * 16 + seg * 4;
                asm volatile("cp.async.cg.shared.global [%0], [%1], 16, %2;"
                             :: "r"(sl), "l"(gl), "r"(sz));
            }
        }
#pragma unroll
        for (int j = 0; j < 2; j++) {
            int u = tid + j * 256;
            int row = u >> 5, seg = u & 31;
            unsigned sb = base + (ASZ + row * BP2 + seg * 4) * 4;
            const unsigned* gh = Whi + (size_t)(ch * 16 + row) * 128 + seg * 4;
            asm volatile("cp.async.cg.shared.global [%0], [%1], 16;"
                         :: "r"(sb), "l"(gh));
            unsigned sl = base + (ASZ + 16 * BP2 + row * BP2 + seg * 4) * 4;
            const unsigned* gl = Wlo + (size_t)(ch * 16 + row) * 128 + seg * 4;
            asm volatile("cp.async.cg.shared.global [%0], [%1], 16;"
                         :: "r"(sl), "l"(gl));
        }
        asm volatile("cp.async.commit_group;");
    };

    stage(0, 0);

    for (int ch = 0; ch < nch; ch++) {
        const int cur = ch & 1;
        if (ch + 1 < nch) {
            stage(ch + 1, cur ^ 1);
            asm volatile("cp.async.wait_group 1;");
        } else {
            asm volatile("cp.async.wait_group 0;");
        }
        __syncthreads();

        const unsigned* AhiS = smem_u + cur * STG;
        const unsigned* AloS = AhiS + 128 * AP2;
        const float*    AfS  = (const float*)(smem_u + cur * STG);
        const unsigned* BhiS = smem_u + cur * STG + ASZ;
        const unsigned* BloS = BhiS + 16 * BP2;

#pragma unroll
        for (int ks = 0; ks < 2; ks++) {
            unsigned ah[4][4], al[4][4];
#pragma unroll
            for (int mf = 0; mf < 4; mf++) {
                if (AMODE == 1) {
                    int base = (wr * 64 + mf * 16 + qid) * AP2 + ks * 8 + qtr;
                    ah[mf][0] = AhiS[base];
                    ah[mf][1] = AhiS[base + 8 * AP2];
                    ah[mf][2] = AhiS[base + 4];
                    ah[mf][3] = AhiS[base + 8 * AP2 + 4];
                    al[mf][0] = AloS[base];
                    al[mf][1] = AloS[base + 8 * AP2];
                    al[mf][2] = AloS[base + 4];
                    al[mf][3] = AloS[base + 8 * AP2 + 4];
                } else {
                    const float* p = AfS + (wr * 64 + mf * 16 + qid) * 36 + ks * 16 + 2 * qtr;
                    float2 f0 = *(const float2*)p;
                    float2 f1 = *(const float2*)(p + 8 * 36);
                    float2 f2 = *(const float2*)(p + 8);
                    float2 f3 = *(const float2*)(p + 8 * 36 + 8);
                    split_bf2(f0.x, f0.y, ah[mf][0], al[mf][0]);
                    split_bf2(f1.x, f1.y, ah[mf][1], al[mf][1]);
                    split_bf2(f2.x, f2.y, ah[mf][2], al[mf][2]);
                    split_bf2(f3.x, f3.y, ah[mf][3], al[mf][3]);
                }
            }
            unsigned bh[4][2], bl[4][2];
#pragma unroll
            for (int nf = 0; nf < 4; nf++) {
                int bw = (ks * 8 + qtr) * BP2 + wc * 32 + nf * 8 + qid;
                bh[nf][0] = BhiS[bw];
                bh[nf][1] = BhiS[bw + 4 * BP2];
                bl[nf][0] = BloS[bw];
                bl[nf][1] = BloS[bw + 4 * BP2];
            }
#pragma unroll
            for (int mf = 0; mf < 4; mf++)
#pragma unroll
                for (int nf = 0; nf < 4; nf++) {
                    mma_bf16(acc[mf][nf], ah[mf], bh[nf]);
                    mma_bf16(acc[mf][nf], ah[mf], bl[nf]);
                    mma_bf16(acc[mf][nf], al[mf], bh[nf]);
                }
        }
        __syncthreads();
    }

    // ---- epilogue: bias (+resid via rmap), write C (+ optional P-prep) ----
#pragma unroll
    for (int mf = 0; mf < 4; mf++) {
        int r0 = bm + wr * 64 + mf * 16 + qid;
        int rr0 = 0, rr1 = 0;
        if (resid) {
            if (r0 < M)     rr0 = rmap ? __ldg(rmap + r0)     : r0;
            if (r0 + 8 < M) rr1 = rmap ? __ldg(rmap + r0 + 8) : r0 + 8;
        }
#pragma unroll
        for (int nf = 0; nf < 4; nf++) {
            int c0 = wc * 32 + nf * 8 + qtr * 2;
            float2 bv = *(const float2*)&bias[c0];
            if (r0 < M) {
                float2 o;
                o.x = acc[mf][nf][0] + bv.x;
                o.y = acc[mf][nf][1] + bv.y;
                if (resid) {
                    float2 rv = *(const float2*)&resid[(size_t)rr0 * 128 + c0];
                    o.x += rv.x; o.y += rv.y;
                }
                *(float2*)&C[(size_t)r0 * 128 + c0] = o;
                if (Pout) {
                    float m0 = fmaxf(o.x, 0.f) + 1e-7f, w0 = __expf(m0);
                    float m1 = fmaxf(o.y, 0.f) + 1e-7f, w1 = __expf(m1);
                    Pout[(size_t)r0 * 128 + c0]     = __floats2half2_rn(w0, m0 * w0);
                    Pout[(size_t)r0 * 128 + c0 + 1] = __floats2half2_rn(w1, m1 * w1);
                }
            }
            if (r0 + 8 < M) {
                float2 o;
                o.x = acc[mf][nf][2] + bv.x;
                o.y = acc[mf][nf][3] + bv.y;
                if (resid) {
                    float2 rv = *(const float2*)&resid[(size_t)rr1 * 128 + c0];
                    o.x += rv.x; o.y += rv.y;
                }
                *(float2*)&C[(size_t)(r0 + 8) * 128 + c0] = o;
                if (Pout) {
                    float m0 = fmaxf(o.x, 0.f) + 1e-7f, w0 = __expf(m0);
                    float m1 = fmaxf(o.y, 0.f) + 1e-7f, w1 = __expf(m1);
                    Pout[(size_t)(r0 + 8) * 128 + c0]     = __floats2half2_rn(w0, m0 * w0);
                    Pout[(size_t)(r0 + 8) * 128 + c0 + 1] = __floats2half2_rn(w1, m1 * w1);
                }
            }
        }
    }
}

// ======================= CSR build kernels (both sets batched) ==============
__global__ void cs_zero(int* __restrict__ a, int n) {
    int i = blockIdx.x * blockDim.x + threadIdx.x;
    if (i < n) a[i] = 0;
}

__global__ void cs_hist2(const int* __restrict__ dst, int* __restrict__ cnt) {
    int e = blockIdx.x * blockDim.x + threadIdx.x;
    if (e >= 2 * EE) return;
    int set = e >= EE;
    atomicAdd(cnt + set * NN + __ldg(dst + e), 1);
}

__global__ void cs_scan1_2(const int* __restrict__ cnt, int* __restrict__ S,
                           int* __restrict__ bsum) {
    __shared__ int sm[256];
    int set = blockIdx.x / NCHUNK;
    int c   = blockIdx.x % NCHUNK;
    int t = threadIdx.x;
    const int* cntS = cnt + set * NN;
    int* SS = S + set * NN;
    int base = c * SCHUNK + t * 4;
    int v0 = (base + 0 < NN) ? cntS[base + 0] : 0;
    int v1 = (base + 1 < NN) ? cntS[base + 1] : 0;
    int v2 = (base + 2 < NN) ? cntS[base + 2] : 0;
    int v3 = (base + 3 < NN) ? cntS[base + 3] : 0;
    int l1 = v0 + v1, l2 = l1 + v2, l3 = l2 + v3;
    sm[t] = l3;
    __syncthreads();
    for (int off = 1; off < 256; off <<= 1) {
        int x = (t >= off) ? sm[t - off] : 0;
        __syncthreads();
        sm[t] += x;
        __syncthreads();
    }
    int excl = sm[t] - l3;
    if (base + 0 < NN) SS[base + 0] = excl + v0;
    if (base + 1 < NN) SS[base + 1] = excl + l1;
    if (base + 2 < NN) SS[base + 2] = excl + l2;
    if (base + 3 < NN) SS[base + 3] = excl + l3;
    if (t == 255) bsum[set * NCHUNK + c] = sm[255];
}

__global__ void cs_scan2_2(int* __restrict__ bsum) {
    __shared__ int sm[128];
    int set = blockIdx.x;
    int t = threadIdx.x;
    int* bs = bsum + set * NCHUNK;
    int v = (t < NCHUNK) ? bs[t] : 0;
    sm[t] = v;
    __syncthreads();
    for (int off = 1; off < 128; off <<= 1) {
        int x = (t >= off) ? sm[t - off] : 0;
        __syncthreads();
        sm[t] += x;
        __syncthreads();
    }
    if (t < NCHUNK) bs[t] = sm[t] - v;
}

__global__ void cs_scan3_2(const int* __restrict__ S, const int* __restrict__ boff,
                           int* __restrict__ rs, int* __restrict__ cur) {
    int idx = blockIdx.x * blockDim.x + threadIdx.x;
    int set = idx / (NN + 1);
    int i   = idx % (NN + 1);
    if (set >= 2) return;
    const int* SS = S + set * NN;
    const int* bo = boff + set * NCHUNK;
    int val = (i == 0) ? 0 : SS[i - 1] + bo[(i - 1) >> 10];
    rs[set * (NN + 1) + i] = val;
    if (i < NN) cur[set * NN + i] = val;
}

__global__ void cs_scatter2(const int* __restrict__ src, const int* __restrict__ dst,
                            int* __restrict__ cur, int* __restrict__ eidx) {
    int e = blockIdx.x * blockDim.x + threadIdx.x;
    if (e >= 2 * EE) return;
    int set = e >= EE;
    int d = __ldg(dst + e);
    int pos = atomicAdd(cur + set * NN + d, 1);
    eidx[set * EE + pos] = __ldg(src + e);
}

// ---------------- CSR aggregation: split-packed out = agg(d) + h[d] ---------
// Row w in [0,M). d = dmap ? dmap[w] : w (CSR row + h row); output row = w.
__global__ void agg_kernel(const int* __restrict__ rs, const int* __restrict__ eidx,
                           const __half2* __restrict__ P, const float* __restrict__ h,
                           const int* __restrict__ dmap,
                           unsigned* __restrict__ outhi, unsigned* __restrict__ outlo,
                           int M) {
    int w = (blockIdx.x * blockDim.x + threadIdx.x) >> 5;
    int lane = threadIdx.x & 31;
    if (w >= M) return;
    int d = dmap ? __ldg(dmap + w) : w;
    int beg = __ldg(rs + d), end = __ldg(rs + d + 1);
    float s0 = 0.f, t0 = 0.f, s1 = 0.f, t1 = 0.f;
    float s2 = 0.f, t2 = 0.f, s3 = 0.f, t3 = 0.f;
    int j = beg;
    for (; j + 2 <= end; j += 2) {
        int a = __ldg(eidx + j);
        int b = __ldg(eidx + j + 1);
        uint4 pa = __ldg((const uint4*)(P + (size_t)a * 128) + lane);
        uint4 pb = __ldg((const uint4*)(P + (size_t)b * 128) + lane);
        float2 f;
        f = __half22float2(*(__half2*)&pa.x); s0 += f.x; t0 += f.y;
        f = __half22float2(*(__half2*)&pa.y); s1 += f.x; t1 += f.y;
        f = __half22float2(*(__half2*)&pa.z); s2 += f.x; t2 += f.y;
        f = __half22float2(*(__half2*)&pa.w); s3 += f.x; t3 += f.y;
        f = __half22float2(*(__half2*)&pb.x); s0 += f.x; t0 += f.y;
        f = __half22float2(*(__half2*)&pb.y); s1 += f.x; t1 += f.y;
        f = __half22float2(*(__half2*)&pb.z); s2 += f.x; t2 += f.y;
        f = __half22float2(*(__half2*)&pb.w); s3 += f.x; t3 += f.y;
    }
    if (j < end) {
        int a = __ldg(eidx + j);
        uint4 pa = __ldg((const uint4*)(P + (size_t)a * 128) + lane);
        float2 f;
        f = __half22float2(*(__half2*)&pa.x); s0 += f.x; t0 += f.y;
        f = __half22float2(*(__half2*)&pa.y); s1 += f.x; t1 += f.y;
        f = __half22float2(*(__half2*)&pa.z); s2 += f.x; t2 += f.y;
        f = __half22float2(*(__half2*)&pa.w); s3 += f.x; t3 += f.y;
    }
    float4 hv = *(const float4*)(h + (size_t)d * 128 + lane * 4);
    float o0 = t0 / (s0 + 1e-16f) + hv.x;
    float o1 = t1 / (s1 + 1e-16f) + hv.y;
    float o2 = t2 / (s2 + 1e-16f) + hv.z;
    float o3 = t3 / (s3 + 1e-16f) + hv.w;
    uint2 hv2, lv2;
    split_bf2(o0, o1, hv2.x, lv2.x);
    split_bf2(o2, o3, hv2.y, lv2.y);
    *(uint2*)(outhi + (size_t)w * 64 + lane * 2) = hv2;
    *(uint2*)(outlo + (size_t)w * 64 + lane * 2) = lv2;
}

// ---------------- LayerNorm + ReLU + P-prep (warp per row, opt gather) ------
__global__ void ln_relu_prep_kernel(const float* __restrict__ in,
                                    const int*   __restrict__ map,
                                    const float* __restrict__ g,
                                    const float* __restrict__ b,
                                    float* __restrict__ out,
                                    __half2* __restrict__ P, int M) {
    int gw   = (blockIdx.x * blockDim.x + threadIdx.x) >> 5;
    int lane = threadIdx.x & 31;
    if (gw >= M) return;
    int srow = map ? __ldg(map + gw) : gw;
    float4 v = *(const float4*)&in[(size_t)srow * HH + lane * 4];
    float s = v.x + v.y + v.z + v.w;
#pragma unroll
    for (int o = 16; o; o >>= 1) s += __shfl_xor_sync(0xffffffffu, s, o);
    float mu = s * (1.f / 128.f);
    float dx = v.x - mu, dy = v.y - mu, dz = v.z - mu, dw = v.w - mu;
    float q = dx * dx + dy * dy + dz * dz + dw * dw;
#pragma unroll
    for (int o = 16; o; o >>= 1) q += __shfl_xor_sync(0xffffffffu, q, o);
    float rs = rsqrtf(q * (1.f / 128.f) + 1e-5f);
    float4 gv = *(const float4*)&g[lane * 4];
    float4 bv = *(const float4*)&b[lane * 4];
    float4 o4;
    o4.x = fmaxf(dx * rs * gv.x + bv.x, 0.f);
    o4.y = fmaxf(dy * rs * gv.y + bv.y, 0.f);
    o4.z = fmaxf(dz * rs * gv.z + bv.z, 0.f);
    o4.w = fmaxf(dw * rs * gv.w + bv.w, 0.f);
    *(float4*)&out[(size_t)gw * HH + lane * 4] = o4;
    float m0 = o4.x + 1e-7f, m1 = o4.y + 1e-7f, m2 = o4.z + 1e-7f, m3 = o4.w + 1e-7f;
    float w0 = __expf(m0), w1 = __expf(m1), w2 = __expf(m2), w3 = __expf(m3);
    __half2 p[4];
    p[0] = __floats2half2_rn(w0, m0 * w0);
    p[1] = __floats2half2_rn(w1, m1 * w1);
    p[2] = __floats2half2_rn(w2, m2 * w2);
    p[3] = __floats2half2_rn(w3, m3 * w3);
    *(uint4*)(P + (size_t)gw * 128 + lane * 4) = *(uint4*)p;
}

// ---------------- final: LN + ReLU + pred + log_softmax (row = blockIdx) ----
__global__ void final_kernel(const float* __restrict__ h,
                             const float* __restrict__ g,
                             const float* __restrict__ b,
                             const float* __restrict__ pw,
                             const float* __restrict__ pb,
                             float* __restrict__ out) {
    __shared__ float sv[128];
    __shared__ float sl[CC];
    __shared__ float red[4];
    __shared__ float stats[2];
    int t = threadIdx.x;
    int lane = t & 31, warp = t >> 5;
    int row = blockIdx.x;
    float x = h[(size_t)row * HH + t];
    float s = x;
#pragma unroll
    for (int o = 16; o; o >>= 1) s += __shfl_xor_sync(0xffffffffu, s, o);
    if (lane == 0) red[warp] = s;
    __syncthreads();
    float mu = (red[0] + red[1] + red[2] + red[3]) * (1.f / 128.f);
    float d = x - mu;
    float q = d * d;
#pragma unroll
    for (int o = 16; o; o >>= 1) q += __shfl_xor_sync(0xffffffffu, q, o);
    __syncthreads();
    if (lane == 0) red[warp] = q;
    __syncthreads();
    float var = (red[0] + red[1] + red[2] + red[3]) * (1.f / 128.f);
    float rs = rsqrtf(var + 1e-5f);
    sv[t] = fmaxf(d * rs * g[t] + b[t], 0.f);
    __syncthreads();
    if (t < CC) {
        float a = pb[t];
#pragma unroll 8
        for (int k = 0; k < 128; k++) a += sv[k] * pw[k * CC + t];
        sl[t] = a;
    }
    __syncthreads();
    if (t == 0) {
        float mx = -1e30f;
        for (int c = 0; c < CC; c++) mx = fmaxf(mx, sl[c]);
        float se = 0.f;
        for (int c = 0; c < CC; c++) se += expf(sl[c] - mx);
        stats[0] = mx; stats[1] = logf(se);
    }
    __syncthreads();
    if (t < CC) out[blockIdx.x * CC + t] = sl[t] - stats[0] - stats[1];
}

// ---------------- host orchestration ----------------------------------------
extern "C" void kernel_launch(void* const* d_in, const int* in_sizes, int n_in,
                              void* d_out, int out_size) {
    const float* x        = (const float*)d_in[0];
    const int*   src      = (const int*)  d_in[1];
    const int*   dst      = (const int*)  d_in[2];
    const int*   node_map = (const int*)  d_in[3];
    const int*   fmap     = (const int*)  d_in[4];
    const float* enc_w    = (const float*)d_in[5];
    const float* enc_b    = (const float*)d_in[6];
    const float* gcn_w    = (const float*)d_in[7];
    const float* gcn_b    = (const float*)d_in[8];
    const float* ln_g     = (const float*)d_in[9];
    const float* ln_b     = (const float*)d_in[10];
    const float* pred_w   = (const float*)d_in[11];
    const float* pred_b   = (const float*)d_in[12];
    float* out = (float*)d_out;

    float *bA, *bB, *bC;
    __half2* P;
    unsigned* wimg;
    int *rs, *cur, *eidx, *S, *bsum, *cmap;
    cudaGetSymbolAddress((void**)&bA,   g_bufA);
    cudaGetSymbolAddress((void**)&bB,   g_bufB);
    cudaGetSymbolAddress((void**)&bC,   g_bufC);
    cudaGetSymbolAddress((void**)&P,    g_P);
    cudaGetSymbolAddress((void**)&wimg, g_wimg);
    cudaGetSymbolAddress((void**)&rs,   g_rs);
    cudaGetSymbolAddress((void**)&cur,  g_cur);
    cudaGetSymbolAddress((void**)&eidx, g_eidx);
    cudaGetSymbolAddress((void**)&S,    g_S);
    cudaGetSymbolAddress((void**)&bsum, g_bsum);
    cudaGetSymbolAddress((void**)&cmap, g_cmap);

    unsigned* bChi = (unsigned*)bC;
    unsigned* bClo = bChi + (size_t)NN * 64;
    int* cmap_dst = cmap;
    int* cmap_res = cmap + NOUTT;

    cudaFuncSetAttribute(gemm_cp_kernel<0>, cudaFuncAttributeMaxDynamicSharedMemorySize, GSMEM_MAX);
    cudaFuncSetAttribute(gemm_cp_kernel<1>, cudaFuncAttributeMaxDynamicSharedMemorySize, GSMEM_MAX);

    const int gemmGrid = (NN + 127) / 128;
    const int gemm2Grid = (NOUTT + 127) / 128;
    const int rowGrid  = (NN * 32 + 255) / 256;
    const int aggCGrid = (NOUTT * 32 + 255) / 256;
    const int e2Grid   = (2 * EE + 255) / 256;

    // weight split + layer-2 map composition (once per call)
    prep_w_kernel<<<(40960 + 255) / 256, 256>>>(enc_w, gcn_w, wimg);
    compose_map_kernel<<<(NOUTT + 255) / 256, 256>>>(node_map, fmap, cmap_dst, cmap_res);

    // ---- CSR build for both edge sets, batched ----
    cs_zero    <<<(2 * NN + 255) / 256, 256>>>(cur, 2 * NN);
    cs_hist2   <<<e2Grid, 256>>>(dst, cur);
    cs_scan1_2 <<<2 * NCHUNK, 256>>>(cur, S, bsum);
    cs_scan2_2 <<<2, 128>>>(bsum);
    cs_scan3_2 <<<(2 * (NN + 1) + 255) / 256, 256>>>(S, bsum, rs, cur);
    cs_scatter2<<<e2Grid, 256>>>(src, dst, cur, eidx);

    // encoder: bA = x @ enc_w + enc_b (fused P-prep)
    gemm_cp_kernel<0><<<gemmGrid, 256, GSMEM_MAX>>>(
        x, nullptr, nullptr, FINN, wimg + ENC_HI, wimg + ENC_LO,
        enc_b, nullptr, nullptr, bA, P, NN);

    // conv0: split-packed bC = agg(set0) + bA; bB = bC @ W0 + b0
    agg_kernel<<<rowGrid, 256>>>(rs, eidx, P, bA, nullptr, bChi, bClo, NN);
    gemm_cp_kernel<1><<<gemmGrid, 256, GSMEM_MAX>>>(
        nullptr, bChi, bClo, HH, wimg + WM_HI(0), wimg + WM_LO(0),
        gcn_b, nullptr, nullptr, bB, nullptr, NN);

    // layer 1: h2 = relu(LN(bB)) -> bA (+P); bC = agg(set0)+bA; bA = bC@W1+b1+bB
    ln_relu_prep_kernel<<<rowGrid, 256>>>(bB, nullptr, ln_g, ln_b, bA, P, NN);
    agg_kernel<<<rowGrid, 256>>>(rs, eidx, P, bA, nullptr, bChi, bClo, NN);
    gemm_cp_kernel<1><<<gemmGrid, 256, GSMEM_MAX>>>(
        nullptr, bChi, bClo, HH, wimg + WM_HI(1), wimg + WM_LO(1),
        gcn_b + HH, bB, nullptr, bA, nullptr, NN);

    // layer 2 (COMPACTED to the 10k seed rows):
    //   h2 = relu(LN(bA[map0])) -> bB (+P, moved space, full width — P needed at any src)
    //   compact agg: row b -> d = cmap_dst[b]; bC[b] = agg(set1, d) + bB[d]
    //   compact GEMM: bB[b] = bC[b]@W2 + b2 + bA[cmap_res[b]]
    ln_relu_prep_kernel<<<rowGrid, 256>>>(bA, node_map, ln_g + HH, ln_b + HH, bB, P, NN);
    agg_kernel<<<aggCGrid, 256>>>(rs + (NN + 1), eidx + EE, P, bB, cmap_dst,
                                  bChi, bClo, NOUTT);
    gemm_cp_kernel<1><<<gemm2Grid, 256, GSMEM_MAX>>>(
        nullptr, bChi, bClo, HH, wimg + WM_HI(2), wimg + WM_LO(2),
        gcn_b + 2 * HH, bA, cmap_res, bB, nullptr, NOUTT);

    // final: row b directly; LN+ReLU+pred+log_softmax
    final_kernel<<<NOUTT, 128>>>(bB, ln_g + 2 * HH, ln_b + 2 * HH, pred_w, pred_b, out);
}